// round 1
// baseline (speedup 1.0000x reference)
#include <cuda_runtime.h>
#include <math.h>
#include <stdint.h>

#define BB 4
#define SS 4096
#define DD 128
#define HH 256
#define ROWS (BB*SS)   // 16384

// ---------------- scratch (no allocations allowed) ----------------
__device__ float g_normed[ROWS*DD];   // 8 MB
__device__ float g_gate[ROWS*HH];     // 16 MB
__device__ float g_v[ROWS*HH];        // 16 MB
__device__ float g_q[ROWS*DD];        // 8 MB
__device__ float g_k[ROWS*DD];        // 8 MB
__device__ float g_av[ROWS*HH];       // 16 MB

// ---------------- packed f32x2 helpers (FFMA2 = 2x fp32 rate on sm_103a) ---
__device__ __forceinline__ unsigned long long dup2(float x) {
    unsigned int u = __float_as_uint(x);
    unsigned long long r;
    asm("mov.b64 %0, {%1,%1};" : "=l"(r) : "r"(u));
    return r;
}
__device__ __forceinline__ void ffma2(unsigned long long &acc,
                                      unsigned long long a,
                                      unsigned long long b) {
    asm("fma.rn.f32x2 %0, %1, %2, %0;" : "+l"(acc) : "l"(a), "l"(b));
}
__device__ __forceinline__ float2 unpk(unsigned long long v) {
    unsigned int lo, hi;
    asm("mov.b64 {%0,%1}, %2;" : "=r"(lo), "=r"(hi) : "l"(v));
    float2 f; f.x = __uint_as_float(lo); f.y = __uint_as_float(hi);
    return f;
}
__device__ __forceinline__ float silu_f(float x) {
    return x / (1.0f + expf(-x));
}

// 8x8 micro-tile, K-chunk of 8, accumulate in packed f32x2 pairs along N.
template<int LDA, int LDB>
__device__ __forceinline__ void micro_fma(const float (*As)[LDA],
                                          const float (*Bs)[LDB],
                                          unsigned long long (&acc)[8][4],
                                          int mb, int nb) {
    #pragma unroll
    for (int kk = 0; kk < 8; kk++) {
        float4 a0 = *(const float4*)&As[kk][mb];
        float4 a1 = *(const float4*)&As[kk][mb + 4];
        unsigned long long a2[8];
        a2[0] = dup2(a0.x); a2[1] = dup2(a0.y); a2[2] = dup2(a0.z); a2[3] = dup2(a0.w);
        a2[4] = dup2(a1.x); a2[5] = dup2(a1.y); a2[6] = dup2(a1.z); a2[7] = dup2(a1.w);
        unsigned long long bb[4];
        #pragma unroll
        for (int p = 0; p < 4; p++)
            bb[p] = *(const unsigned long long*)&Bs[kk][nb + 2*p];
        #pragma unroll
        for (int i = 0; i < 8; i++)
            #pragma unroll
            for (int p = 0; p < 4; p++)
                ffma2(acc[i][p], a2[i], bb[p]);
    }
}

// ---------------- kernel 1: rope + layernorm ----------------
__global__ void prep_kernel(const float* __restrict__ q,
                            const float* __restrict__ g,
                            const float* __restrict__ b,
                            float* __restrict__ o) {
    const int row = blockIdx.x;         // 0..16383
    const int d = threadIdx.x;          // 0..127
    const int t = row & (SS - 1);       // position within sequence
    float x = q[(size_t)row * DD + d];
    float y = x;
    if (d < 32) {                       // warp 0 only, full warp active
        int j = d >> 1;
        double dinv = pow(10000.0, -(double)j / 16.0);
        float f = (float)t * (float)dinv;
        float c = cosf(f), s = sinf(f);
        float partner = __shfl_xor_sync(0xffffffffu, x, 1);
        y = (d & 1) ? (x * c + partner * s) : (x * c - partner * s);
    }
    // layernorm over 128
    __shared__ float red[4];
    float v = y;
    #pragma unroll
    for (int o2 = 16; o2; o2 >>= 1) v += __shfl_xor_sync(0xffffffffu, v, o2);
    if ((threadIdx.x & 31) == 0) red[threadIdx.x >> 5] = v;
    __syncthreads();
    float mu = (red[0] + red[1] + red[2] + red[3]) * (1.0f / 128.0f);
    float dv = y - mu;
    float v2 = dv * dv;
    __syncthreads();
    #pragma unroll
    for (int o2 = 16; o2; o2 >>= 1) v2 += __shfl_xor_sync(0xffffffffu, v2, o2);
    if ((threadIdx.x & 31) == 0) red[threadIdx.x >> 5] = v2;
    __syncthreads();
    float var = (red[0] + red[1] + red[2] + red[3]) * (1.0f / 128.0f);
    float rs = rsqrtf(var + 1e-5f);
    o[(size_t)row * DD + d] = dv * rs * g[d] + b[d];
}

// ---------------- small GEMMs: X[16384,KDIM] @ W[KDIM,NDIM] + epilogue -----
// MODE 0: silu -> O0
// MODE 1: silu, then two affines (q = y*gam0+bet0 -> O0, k = y*gam1+bet1 -> O1)
// MODE 2: A elementwise-multiplied by Amul before GEMM; bias only -> O0
template<int KDIM, int NDIM, int MODE>
__global__ __launch_bounds__(256) void gemm_small(
    const float* __restrict__ A, const float* __restrict__ Amul,
    const float* __restrict__ W, const float* __restrict__ bias,
    const float* __restrict__ gam, const float* __restrict__ bet,
    float* __restrict__ O0, float* __restrict__ O1)
{
    constexpr int BN = NDIM;
    constexpr int BM = 16384 / BN;    // 64 (N=256) or 128 (N=128)
    constexpr int TX = BN / 8;
    __shared__ float As[8][BM + 4];
    __shared__ float Bs[8][BN + 4];
    const int tid = threadIdx.x;
    const int tx = tid % TX, ty = tid / TX;
    const int m0 = blockIdx.x * BM;
    const int mb = ty * 8, nb = tx * 8;
    unsigned long long acc[8][4];
    #pragma unroll
    for (int i = 0; i < 8; i++)
        #pragma unroll
        for (int p = 0; p < 4; p++) acc[i][p] = 0ull;

    for (int k0 = 0; k0 < KDIM; k0 += 8) {
        __syncthreads();
        for (int i = tid; i < BM * 2; i += 256) {
            int r = i >> 1, c4 = i & 1;
            float4 av = *(const float4*)&A[(size_t)(m0 + r) * KDIM + k0 + c4 * 4];
            if (MODE == 2) {
                float4 mv = *(const float4*)&Amul[(size_t)(m0 + r) * KDIM + k0 + c4 * 4];
                av.x *= mv.x; av.y *= mv.y; av.z *= mv.z; av.w *= mv.w;
            }
            As[c4*4+0][r] = av.x; As[c4*4+1][r] = av.y;
            As[c4*4+2][r] = av.z; As[c4*4+3][r] = av.w;
        }
        for (int i = tid; i < BN * 2; i += 256) {
            int r = i / (BN / 4), c = i % (BN / 4);
            *(float4*)&Bs[r][c * 4] = *(const float4*)&W[(size_t)(k0 + r) * NDIM + c * 4];
        }
        __syncthreads();
        micro_fma<BM + 4, BN + 4>(As, Bs, acc, mb, nb);
    }

    #pragma unroll
    for (int i = 0; i < 8; i++) {
        const int m = m0 + mb + i;
        #pragma unroll
        for (int p = 0; p < 4; p++) {
            float2 v = unpk(acc[i][p]);
            #pragma unroll
            for (int e = 0; e < 2; e++) {
                int n = nb + 2 * p + e;
                float x = (e ? v.y : v.x) + bias[n];
                if (MODE == 0) {
                    O0[(size_t)m * NDIM + n] = silu_f(x);
                } else if (MODE == 1) {
                    float y = silu_f(x);
                    O0[(size_t)m * NDIM + n] = y * gam[n] + bet[n];
                    O1[(size_t)m * NDIM + n] = y * gam[NDIM + n] + bet[NDIM + n];
                } else {
                    O0[(size_t)m * NDIM + n] = x;
                }
            }
        }
    }
}

// ---------------- big GEMM 1: att = relu(q @ k^T / S)^2 ----------------
__global__ __launch_bounds__(256, 2) void sim_kernel(const float* __restrict__ q,
                                                     const float* __restrict__ k,
                                                     float* __restrict__ att)
{
    __shared__ float As[8][132];
    __shared__ float Bs[8][132];
    const int b = blockIdx.z;
    const float* qb = q + (size_t)b * SS * DD;
    const float* kb = k + (size_t)b * SS * DD;
    float* ab = att + (size_t)b * SS * SS;
    const int m0 = blockIdx.y * 128, n0 = blockIdx.x * 128;
    const int tid = threadIdx.x;
    const int tx = tid & 15, ty = tid >> 4;
    const int mb = ty * 8, nb = tx * 8;
    const int r = tid >> 1, c4 = tid & 1;
    unsigned long long acc[8][4];
    #pragma unroll
    for (int i = 0; i < 8; i++)
        #pragma unroll
        for (int p = 0; p < 4; p++) acc[i][p] = 0ull;

    for (int k0 = 0; k0 < DD; k0 += 8) {
        __syncthreads();
        float4 a4 = *(const float4*)&qb[(size_t)(m0 + r) * DD + k0 + c4 * 4];
        As[c4*4+0][r] = a4.x; As[c4*4+1][r] = a4.y;
        As[c4*4+2][r] = a4.z; As[c4*4+3][r] = a4.w;
        float4 b4 = *(const float4*)&kb[(size_t)(n0 + r) * DD + k0 + c4 * 4];
        Bs[c4*4+0][r] = b4.x; Bs[c4*4+1][r] = b4.y;
        Bs[c4*4+2][r] = b4.z; Bs[c4*4+3][r] = b4.w;
        __syncthreads();
        micro_fma<132, 132>(As, Bs, acc, mb, nb);
    }

    const float invS = 1.0f / (float)SS;
    #pragma unroll
    for (int i = 0; i < 8; i++) {
        float* rowp = ab + (size_t)(m0 + mb + i) * SS + n0 + nb;
        float2 v0 = unpk(acc[i][0]), v1 = unpk(acc[i][1]);
        float2 v2 = unpk(acc[i][2]), v3 = unpk(acc[i][3]);
        float4 o0, o1;
        {
            float s;
            s = fmaxf(v0.x * invS, 0.0f); o0.x = s * s;
            s = fmaxf(v0.y * invS, 0.0f); o0.y = s * s;
            s = fmaxf(v1.x * invS, 0.0f); o0.z = s * s;
            s = fmaxf(v1.y * invS, 0.0f); o0.w = s * s;
            s = fmaxf(v2.x * invS, 0.0f); o1.x = s * s;
            s = fmaxf(v2.y * invS, 0.0f); o1.y = s * s;
            s = fmaxf(v3.x * invS, 0.0f); o1.z = s * s;
            s = fmaxf(v3.y * invS, 0.0f); o1.w = s * s;
        }
        *(float4*)&rowp[0] = o0;
        *(float4*)&rowp[4] = o1;
    }
}

// ---------------- big GEMM 2: av = att @ v ----------------
__global__ __launch_bounds__(256, 2) void attnv_kernel(const float* __restrict__ att,
                                                       const float* __restrict__ v,
                                                       float* __restrict__ av)
{
    __shared__ float As[8][132];
    __shared__ float Bs[8][132];
    const int b = blockIdx.z;
    const float* ab = att + (size_t)b * SS * SS;
    const float* vb = v + (size_t)b * SS * HH;
    float* ob = av + (size_t)b * SS * HH;
    const int m0 = blockIdx.y * 128, h0 = blockIdx.x * 128;
    const int tid = threadIdx.x;
    const int tx = tid & 15, ty = tid >> 4;
    const int mb = ty * 8, nb = tx * 8;
    const int r = tid >> 1, c4 = tid & 1;
    const int r2 = tid >> 5, c = tid & 31;
    unsigned long long acc[8][4];
    #pragma unroll
    for (int i = 0; i < 8; i++)
        #pragma unroll
        for (int p = 0; p < 4; p++) acc[i][p] = 0ull;

    for (int j0 = 0; j0 < SS; j0 += 8) {
        __syncthreads();
        float4 a4 = *(const float4*)&ab[(size_t)(m0 + r) * SS + j0 + c4 * 4];
        As[c4*4+0][r] = a4.x; As[c4*4+1][r] = a4.y;
        As[c4*4+2][r] = a4.z; As[c4*4+3][r] = a4.w;
        *(float4*)&Bs[r2][c * 4] = *(const float4*)&vb[(size_t)(j0 + r2) * HH + h0 + c * 4];
        __syncthreads();
        micro_fma<132, 132>(As, Bs, acc, mb, nb);
    }

    #pragma unroll
    for (int i = 0; i < 8; i++) {
        float* rowp = ob + (size_t)(m0 + mb + i) * HH + h0 + nb;
        float2 v0 = unpk(acc[i][0]), v1 = unpk(acc[i][1]);
        float2 v2 = unpk(acc[i][2]), v3 = unpk(acc[i][3]);
        *(float4*)&rowp[0] = make_float4(v0.x, v0.y, v1.x, v1.y);
        *(float4*)&rowp[4] = make_float4(v2.x, v2.y, v3.x, v3.y);
    }
}

// ---------------- launch ----------------
extern "C" void kernel_launch(void* const* d_in, const int* in_sizes, int n_in,
                              void* d_out, int out_size)
{
    const float* query  = (const float*)d_in[0];
    // d_in[1] = key (unused by the reference)
    const float* value  = (const float*)d_in[2];
    const float* ln_g   = (const float*)d_in[3];
    const float* ln_b   = (const float*)d_in[4];
    const float* W_gate = (const float*)d_in[5];
    const float* b_gate = (const float*)d_in[6];
    const float* W_qk   = (const float*)d_in[7];
    const float* b_qk   = (const float*)d_in[8];
    const float* os_g   = (const float*)d_in[9];
    const float* os_b   = (const float*)d_in[10];
    const float* W_out  = (const float*)d_in[11];
    const float* b_out  = (const float*)d_in[12];

    float* out = (float*)d_out;                        // [4,4096,128]
    float* att = out + (size_t)ROWS * DD;              // [4,4096,4096]

    float *p_normed, *p_gate, *p_v, *p_q, *p_k, *p_av;
    cudaGetSymbolAddress((void**)&p_normed, g_normed);
    cudaGetSymbolAddress((void**)&p_gate,   g_gate);
    cudaGetSymbolAddress((void**)&p_v,      g_v);
    cudaGetSymbolAddress((void**)&p_q,      g_q);
    cudaGetSymbolAddress((void**)&p_k,      g_k);
    cudaGetSymbolAddress((void**)&p_av,     g_av);

    prep_kernel<<<ROWS, 128>>>(query, ln_g, ln_b, p_normed);
    gemm_small<128, 256, 0><<<ROWS / 64, 256>>>(p_normed, nullptr, W_gate, b_gate,
                                                nullptr, nullptr, p_gate, nullptr);
    gemm_small<128, 256, 0><<<ROWS / 64, 256>>>(value, nullptr, W_gate, b_gate,
                                                nullptr, nullptr, p_v, nullptr);
    gemm_small<128, 128, 1><<<ROWS / 128, 256>>>(p_normed, nullptr, W_qk, b_qk,
                                                 os_g, os_b, p_q, p_k);
    sim_kernel<<<dim3(32, 32, 4), 256>>>(p_q, p_k, att);
    attnv_kernel<<<dim3(2, 32, 4), 256>>>(att, p_v, p_av);
    gemm_small<256, 128, 2><<<ROWS / 128, 256>>>(p_av, p_gate, W_out, b_out,
                                                 nullptr, nullptr, out, nullptr);
}

// round 3
// speedup vs baseline: 2.3336x; 2.3336x over previous
#include <cuda_runtime.h>
#include <cuda_bf16.h>
#include <math.h>
#include <stdint.h>

#define BB 4
#define SS 4096
#define DD 128
#define HH 256
#define ROWS (BB*SS)   // 16384

// ---------------- scratch (no allocations allowed) ----------------
__device__ float g_normed[ROWS*DD];                  // 8 MB
__device__ float g_gate[ROWS*HH];                    // 16 MB
__device__ float g_v[ROWS*HH];                       // 16 MB
__device__ float g_av[ROWS*HH];                      // 16 MB
__device__ __nv_bfloat16 g_vT[HH*ROWS];              // 8 MB  [256][16384]
__device__ __nv_bfloat16 g_qh[ROWS*DD];              // 4 MB
__device__ __nv_bfloat16 g_ql[ROWS*DD];
__device__ __nv_bfloat16 g_kh[ROWS*DD];
__device__ __nv_bfloat16 g_kl[ROWS*DD];
__device__ __nv_bfloat16 g_atth[(size_t)ROWS*SS];    // 134 MB
__device__ __nv_bfloat16 g_attl[(size_t)ROWS*SS];    // 134 MB

// ================= PTX helpers (base ISA only) =================
__device__ __forceinline__ uint32_t smem_u32(const void* p) {
    uint32_t a;
    asm("{ .reg .u64 t; cvta.to.shared.u64 t, %1; cvt.u32.u64 %0, t; }" : "=r"(a) : "l"(p));
    return a;
}
__device__ __forceinline__ void cp16(uint32_t s, const void* g) {
    asm volatile("cp.async.cg.shared.global [%0], [%1], 16;" :: "r"(s), "l"(g) : "memory");
}
__device__ __forceinline__ void cp_commit() { asm volatile("cp.async.commit_group;" ::: "memory"); }
template<int N> __device__ __forceinline__ void cp_wait() {
    asm volatile("cp.async.wait_group %0;" :: "n"(N) : "memory");
}
__device__ __forceinline__ void ldm_x4(uint32_t &r0, uint32_t &r1, uint32_t &r2, uint32_t &r3, uint32_t a) {
    asm volatile("ldmatrix.sync.aligned.m8n8.x4.shared.b16 {%0,%1,%2,%3}, [%4];"
        : "=r"(r0), "=r"(r1), "=r"(r2), "=r"(r3) : "r"(a));
}
__device__ __forceinline__ void ldm_x2(uint32_t &r0, uint32_t &r1, uint32_t a) {
    asm volatile("ldmatrix.sync.aligned.m8n8.x2.shared.b16 {%0,%1}, [%2];"
        : "=r"(r0), "=r"(r1) : "r"(a));
}
__device__ __forceinline__ void mma16816(float (&c)[4], const uint32_t (&a)[4], const uint32_t (&b)[2]) {
    asm volatile("mma.sync.aligned.m16n8k16.row.col.f32.bf16.bf16.f32 "
        "{%0,%1,%2,%3}, {%4,%5,%6,%7}, {%8,%9}, {%0,%1,%2,%3};"
        : "+f"(c[0]), "+f"(c[1]), "+f"(c[2]), "+f"(c[3])
        : "r"(a[0]), "r"(a[1]), "r"(a[2]), "r"(a[3]), "r"(b[0]), "r"(b[1]));
}

// A-frag for m16k16 from k-contiguous [row][k] smem tile (64 cols, 8 chunks, XOR swizzle)
__device__ __forceinline__ void ldsA(uint32_t (&a)[4], uint32_t base, int mrow, int kt, int lid) {
    int g = lid >> 3, r = lid & 7;
    int row = mrow + ((g & 1) << 3) + r;
    int ch = (kt << 1) + (g >> 1);
    ldm_x4(a[0], a[1], a[2], a[3], base + row * 128 + ((ch ^ (row & 7)) << 4));
}
// B-frag for k16n8 from k-contiguous [n][k] smem tile
__device__ __forceinline__ void ldsB(uint32_t (&b)[2], uint32_t base, int nrow, int kt, int lid) {
    int g = (lid >> 3) & 1, r = lid & 7;
    int row = nrow + r;
    int ch = (kt << 1) + g;
    ldm_x2(b[0], b[1], base + row * 128 + ((ch ^ (row & 7)) << 4));
}

// cp.async a [NROWS x 64] bf16 tile (k-contiguous) into swizzled smem; 256 threads
template<int NROWS>
__device__ __forceinline__ void load_tile64(uint32_t sbase, const __nv_bfloat16* g, size_t rstride, int tid) {
    #pragma unroll
    for (int i = 0; i < NROWS * 8; i += 256) {
        int idx = i + tid;
        int r = idx >> 3, c = idx & 7;
        cp16(sbase + r * 128 + ((c ^ (r & 7)) << 4), g + (size_t)r * rstride + c * 8);
    }
}

__device__ __forceinline__ float silu_f(float x) { return x / (1.0f + expf(-x)); }

// ================= FFMA2 helpers for small CUDA-core GEMMs =================
__device__ __forceinline__ unsigned long long dup2(float x) {
    unsigned int u = __float_as_uint(x);
    unsigned long long r;
    asm("mov.b64 %0, {%1,%1};" : "=l"(r) : "r"(u));
    return r;
}
__device__ __forceinline__ void ffma2(unsigned long long &acc, unsigned long long a, unsigned long long b) {
    asm("fma.rn.f32x2 %0, %1, %2, %0;" : "+l"(acc) : "l"(a), "l"(b));
}
__device__ __forceinline__ float2 unpk(unsigned long long v) {
    unsigned int lo, hi;
    asm("mov.b64 {%0,%1}, %2;" : "=r"(lo), "=r"(hi) : "l"(v));
    float2 f; f.x = __uint_as_float(lo); f.y = __uint_as_float(hi);
    return f;
}
template<int LDA, int LDB>
__device__ __forceinline__ void micro_fma(const float (*As)[LDA], const float (*Bs)[LDB],
                                          unsigned long long (&acc)[8][4], int mb, int nb) {
    #pragma unroll
    for (int kk = 0; kk < 8; kk++) {
        float4 a0 = *(const float4*)&As[kk][mb];
        float4 a1 = *(const float4*)&As[kk][mb + 4];
        unsigned long long a2[8];
        a2[0]=dup2(a0.x); a2[1]=dup2(a0.y); a2[2]=dup2(a0.z); a2[3]=dup2(a0.w);
        a2[4]=dup2(a1.x); a2[5]=dup2(a1.y); a2[6]=dup2(a1.z); a2[7]=dup2(a1.w);
        unsigned long long bb[4];
        #pragma unroll
        for (int p = 0; p < 4; p++) bb[p] = *(const unsigned long long*)&Bs[kk][nb + 2*p];
        #pragma unroll
        for (int i = 0; i < 8; i++)
            #pragma unroll
            for (int p = 0; p < 4; p++) ffma2(acc[i][p], a2[i], bb[p]);
    }
}

// ================= kernel 1: rope + layernorm =================
__global__ void prep_kernel(const float* __restrict__ q, const float* __restrict__ g,
                            const float* __restrict__ b, float* __restrict__ o) {
    const int row = blockIdx.x;
    const int d = threadIdx.x;
    const int t = row & (SS - 1);
    float x = q[(size_t)row * DD + d];
    float y = x;
    if (d < 32) {
        int j = d >> 1;
        double dinv = pow(10000.0, -(double)j / 16.0);
        float f = (float)t * (float)dinv;
        float c = cosf(f), s = sinf(f);
        float partner = __shfl_xor_sync(0xffffffffu, x, 1);
        y = (d & 1) ? (x * c + partner * s) : (x * c - partner * s);
    }
    __shared__ float red[4];
    float v = y;
    #pragma unroll
    for (int o2 = 16; o2; o2 >>= 1) v += __shfl_xor_sync(0xffffffffu, v, o2);
    if ((threadIdx.x & 31) == 0) red[threadIdx.x >> 5] = v;
    __syncthreads();
    float mu = (red[0] + red[1] + red[2] + red[3]) * (1.0f / 128.0f);
    float dv = y - mu;
    float v2 = dv * dv;
    __syncthreads();
    #pragma unroll
    for (int o2 = 16; o2; o2 >>= 1) v2 += __shfl_xor_sync(0xffffffffu, v2, o2);
    if ((threadIdx.x & 31) == 0) red[threadIdx.x >> 5] = v2;
    __syncthreads();
    float var = (red[0] + red[1] + red[2] + red[3]) * (1.0f / 128.0f);
    float rs = rsqrtf(var + 1e-5f);
    o[(size_t)row * DD + d] = dv * rs * g[d] + b[d];
}

// ================= small GEMMs (CUDA core, FFMA2) =================
// MODE 0: silu -> O0 (f32)
// MODE 1: silu, two affines -> bf16 hi/lo splits (qh,ql,kh,kl)
// MODE 2: A .* Amul before GEMM; bias only -> O0
template<int KDIM, int NDIM, int MODE>
__global__ __launch_bounds__(256) void gemm_small(
    const float* __restrict__ A, const float* __restrict__ Amul,
    const float* __restrict__ W, const float* __restrict__ bias,
    const float* __restrict__ gam, const float* __restrict__ bet,
    float* __restrict__ O0,
    __nv_bfloat16* __restrict__ qh, __nv_bfloat16* __restrict__ ql,
    __nv_bfloat16* __restrict__ kh, __nv_bfloat16* __restrict__ kl)
{
    constexpr int BN = NDIM;
    constexpr int BM = 16384 / BN;
    constexpr int TX = BN / 8;
    __shared__ float As[8][BM + 4];
    __shared__ float Bs[8][BN + 4];
    const int tid = threadIdx.x;
    const int tx = tid % TX, ty = tid / TX;
    const int m0 = blockIdx.x * BM;
    const int mb = ty * 8, nb = tx * 8;
    unsigned long long acc[8][4];
    #pragma unroll
    for (int i = 0; i < 8; i++)
        #pragma unroll
        for (int p = 0; p < 4; p++) acc[i][p] = 0ull;

    for (int k0 = 0; k0 < KDIM; k0 += 8) {
        __syncthreads();
        for (int i = tid; i < BM * 2; i += 256) {
            int r = i >> 1, c4 = i & 1;
            float4 av = *(const float4*)&A[(size_t)(m0 + r) * KDIM + k0 + c4 * 4];
            if (MODE == 2) {
                float4 mv = *(const float4*)&Amul[(size_t)(m0 + r) * KDIM + k0 + c4 * 4];
                av.x *= mv.x; av.y *= mv.y; av.z *= mv.z; av.w *= mv.w;
            }
            As[c4*4+0][r] = av.x; As[c4*4+1][r] = av.y;
            As[c4*4+2][r] = av.z; As[c4*4+3][r] = av.w;
        }
        for (int i = tid; i < BN * 2; i += 256) {
            int r = i / (BN / 4), c = i % (BN / 4);
            *(float4*)&Bs[r][c * 4] = *(const float4*)&W[(size_t)(k0 + r) * NDIM + c * 4];
        }
        __syncthreads();
        micro_fma<BM + 4, BN + 4>(As, Bs, acc, mb, nb);
    }

    #pragma unroll
    for (int i = 0; i < 8; i++) {
        const int m = m0 + mb + i;
        #pragma unroll
        for (int p = 0; p < 4; p++) {
            float2 v = unpk(acc[i][p]);
            #pragma unroll
            for (int e = 0; e < 2; e++) {
                int n = nb + 2 * p + e;
                float x = (e ? v.y : v.x) + bias[n];
                if (MODE == 0) {
                    O0[(size_t)m * NDIM + n] = silu_f(x);
                } else if (MODE == 1) {
                    float y = silu_f(x);
                    float yq = y * gam[n] + bet[n];
                    float yk = y * gam[NDIM + n] + bet[NDIM + n];
                    __nv_bfloat16 h0 = __float2bfloat16(yq);
                    __nv_bfloat16 l0 = __float2bfloat16(yq - __bfloat162float(h0));
                    __nv_bfloat16 h1 = __float2bfloat16(yk);
                    __nv_bfloat16 l1 = __float2bfloat16(yk - __bfloat162float(h1));
                    qh[(size_t)m * NDIM + n] = h0; ql[(size_t)m * NDIM + n] = l0;
                    kh[(size_t)m * NDIM + n] = h1; kl[(size_t)m * NDIM + n] = l1;
                } else {
                    O0[(size_t)m * NDIM + n] = x;
                }
            }
        }
    }
}

// ================= v transpose -> bf16 vT [256][16384] =================
__global__ void transpose_kernel(const float* __restrict__ v, __nv_bfloat16* __restrict__ vt) {
    __shared__ float tile[32][33];
    int x = blockIdx.x * 32 + threadIdx.x;   // col in v (0..255)
    int y = blockIdx.y * 32 + threadIdx.y;   // row in v
    #pragma unroll
    for (int dy = 0; dy < 32; dy += 8)
        tile[threadIdx.y + dy][threadIdx.x] = v[(size_t)(y + dy) * HH + x];
    __syncthreads();
    int xo = blockIdx.y * 32 + threadIdx.x;
    int yo = blockIdx.x * 32 + threadIdx.y;
    #pragma unroll
    for (int dy = 0; dy < 32; dy += 8)
        vt[(size_t)(yo + dy) * ROWS + xo] = __float2bfloat16(tile[threadIdx.x][threadIdx.y + dy]);
}

// ================= big GEMM 1: att = relu(q@k^T/S)^2  (HMMA bf16 3-pass) ===
// CTA 128x128, K=128 in two pipelined 64-halves. Stage: Ah|Al|Bh|Bl 16KB each.
#define SIM_STG 65536
#define SIM_SMEM (2*SIM_STG)

__global__ __launch_bounds__(256) void sim_mma(
    const __nv_bfloat16* __restrict__ qh_g, const __nv_bfloat16* __restrict__ ql_g,
    const __nv_bfloat16* __restrict__ kh_g, const __nv_bfloat16* __restrict__ kl_g,
    float* __restrict__ att,
    __nv_bfloat16* __restrict__ atth, __nv_bfloat16* __restrict__ attl)
{
    extern __shared__ __align__(128) char smem[];
    const uint32_t sb = smem_u32(smem);
    const int tid = threadIdx.x, wid = tid >> 5, lid = tid & 31;
    const int b = blockIdx.z, m0 = blockIdx.y * 128, n0 = blockIdx.x * 128;
    const __nv_bfloat16* qhp = qh_g + ((size_t)b * SS + m0) * DD;
    const __nv_bfloat16* qlp = ql_g + ((size_t)b * SS + m0) * DD;
    const __nv_bfloat16* khp = kh_g + ((size_t)b * SS + n0) * DD;
    const __nv_bfloat16* klp = kl_g + ((size_t)b * SS + n0) * DD;

    const int wm = (wid >> 2) * 64, wn = (wid & 3) * 32;
    float acc[4][4][4];
    #pragma unroll
    for (int i = 0; i < 4; i++)
        #pragma unroll
        for (int j = 0; j < 4; j++)
            #pragma unroll
            for (int e = 0; e < 4; e++) acc[i][j][e] = 0.f;

    auto load_half = [&](int h, uint32_t base) {
        load_tile64<128>(base,         qhp + h * 64, DD, tid);
        load_tile64<128>(base + 16384, qlp + h * 64, DD, tid);
        load_tile64<128>(base + 32768, khp + h * 64, DD, tid);
        load_tile64<128>(base + 49152, klp + h * 64, DD, tid);
        cp_commit();
    };
    auto compute = [&](uint32_t base) {
        const uint32_t Ah = base, Al = base + 16384, Bh = base + 32768, Bl = base + 49152;
        #pragma unroll
        for (int kt = 0; kt < 4; kt++) {
            uint32_t bh[4][2], bl[4][2], ah[4][4], al[4][4];
            #pragma unroll
            for (int nt = 0; nt < 4; nt++) { ldsB(bh[nt], Bh, wn + nt*8, kt, lid); ldsB(bl[nt], Bl, wn + nt*8, kt, lid); }
            #pragma unroll
            for (int mt = 0; mt < 4; mt++) ldsA(ah[mt], Ah, wm + mt*16, kt, lid);
            #pragma unroll
            for (int mt = 0; mt < 4; mt++)
                #pragma unroll
                for (int nt = 0; nt < 4; nt++) mma16816(acc[mt][nt], ah[mt], bh[nt]);
            #pragma unroll
            for (int mt = 0; mt < 4; mt++)
                #pragma unroll
                for (int nt = 0; nt < 4; nt++) mma16816(acc[mt][nt], ah[mt], bl[nt]);
            #pragma unroll
            for (int mt = 0; mt < 4; mt++) ldsA(al[mt], Al, wm + mt*16, kt, lid);
            #pragma unroll
            for (int mt = 0; mt < 4; mt++)
                #pragma unroll
                for (int nt = 0; nt < 4; nt++) mma16816(acc[mt][nt], al[mt], bh[nt]);
        }
    };

    load_half(0, sb);
    load_half(1, sb + SIM_STG);
    cp_wait<1>(); __syncthreads();
    compute(sb);
    cp_wait<0>(); __syncthreads();
    compute(sb + SIM_STG);

    // epilogue: a = relu(x/S)^2 ; write f32 att + bf16 hi/lo
    const float invS = 1.0f / (float)SS;
    const int lr = lid >> 2, lc = (lid & 3) * 2;
    float* attb = att + (size_t)b * SS * SS;
    __nv_bfloat16* hib = atth + (size_t)b * SS * SS;
    __nv_bfloat16* lob = attl + (size_t)b * SS * SS;
    #pragma unroll
    for (int mt = 0; mt < 4; mt++) {
        #pragma unroll
        for (int h2 = 0; h2 < 2; h2++) {
            int row = m0 + wm + mt * 16 + h2 * 8 + lr;
            size_t ro = (size_t)row * SS;
            #pragma unroll
            for (int nt = 0; nt < 4; nt++) {
                int col = n0 + wn + nt * 8 + lc;
                float s0 = fmaxf(acc[mt][nt][h2*2+0] * invS, 0.f);
                float s1 = fmaxf(acc[mt][nt][h2*2+1] * invS, 0.f);
                float a0 = s0 * s0, a1 = s1 * s1;
                *(float2*)(attb + ro + col) = make_float2(a0, a1);
                __nv_bfloat16 h0 = __float2bfloat16(a0), h1 = __float2bfloat16(a1);
                __nv_bfloat16 l0 = __float2bfloat16(a0 - __bfloat162float(h0));
                __nv_bfloat16 l1 = __float2bfloat16(a1 - __bfloat162float(h1));
                __nv_bfloat162 hp; hp.x = h0; hp.y = h1;
                __nv_bfloat162 lp; lp.x = l0; lp.y = l1;
                *(__nv_bfloat162*)(hib + ro + col) = hp;
                *(__nv_bfloat162*)(lob + ro + col) = lp;
            }
        }
    }
}

// ================= big GEMM 2: av = (att_hi+att_lo) @ v  (HMMA bf16 2-pass) =
// CTA 128(M) x 256(N=all H), K=4096 in 64 slabs of 64, 3-stage cp.async ring.
// Stage: Ah 16K | Al 16K | B 32K = 64KB; x3 = 192KB.
#define AT_STG 65536
#define AT_SMEM (3*AT_STG)
#define AT_NS 64

__global__ __launch_bounds__(256) void attnv_mma(
    const __nv_bfloat16* __restrict__ atth, const __nv_bfloat16* __restrict__ attl,
    const __nv_bfloat16* __restrict__ vt, float* __restrict__ av)
{
    extern __shared__ __align__(128) char smem[];
    const uint32_t sb = smem_u32(smem);
    const int tid = threadIdx.x, wid = tid >> 5, lid = tid & 31;
    const int b = blockIdx.y, m0 = blockIdx.x * 128;
    const __nv_bfloat16* ahp = atth + (size_t)b * SS * SS + (size_t)m0 * SS;
    const __nv_bfloat16* alp = attl + (size_t)b * SS * SS + (size_t)m0 * SS;
    const __nv_bfloat16* vp  = vt + (size_t)b * SS;

    const int wm = (wid >> 2) * 64, wn = (wid & 3) * 64;
    float acc[4][8][4];
    #pragma unroll
    for (int i = 0; i < 4; i++)
        #pragma unroll
        for (int j = 0; j < 8; j++)
            #pragma unroll
            for (int e = 0; e < 4; e++) acc[i][j][e] = 0.f;

    auto load_slab = [&](int j, int s) {
        uint32_t base = sb + s * AT_STG;
        load_tile64<128>(base,         ahp + j * 64, SS, tid);
        load_tile64<128>(base + 16384, alp + j * 64, SS, tid);
        load_tile64<256>(base + 32768, vp + j * 64, ROWS, tid);
        cp_commit();
    };
    auto compute = [&](int s) {
        uint32_t base = sb + s * AT_STG;
        const uint32_t Ah = base, Al = base + 16384, Bv = base + 32768;
        #pragma unroll
        for (int kt = 0; kt < 4; kt++) {
            uint32_t bf[8][2];
            #pragma unroll
            for (int nt = 0; nt < 8; nt++) ldsB(bf[nt], Bv, wn + nt*8, kt, lid);
            uint32_t af[4][4];
            #pragma unroll
            for (int mt = 0; mt < 4; mt++) ldsA(af[mt], Ah, wm + mt*16, kt, lid);
            #pragma unroll
            for (int mt = 0; mt < 4; mt++)
                #pragma unroll
                for (int nt = 0; nt < 8; nt++) mma16816(acc[mt][nt], af[mt], bf[nt]);
            #pragma unroll
            for (int mt = 0; mt < 4; mt++) ldsA(af[mt], Al, wm + mt*16, kt, lid);
            #pragma unroll
            for (int mt = 0; mt < 4; mt++)
                #pragma unroll
                for (int nt = 0; nt < 8; nt++) mma16816(acc[mt][nt], af[mt], bf[nt]);
        }
    };

    load_slab(0, 0);
    load_slab(1, 1);
    for (int j = 0; j < AT_NS; j++) {
        if (j + 1 < AT_NS) cp_wait<1>(); else cp_wait<0>();
        __syncthreads();
        if (j + 2 < AT_NS) load_slab(j + 2, (j + 2) % 3);
        compute(j % 3);
    }

    const int lr = lid >> 2, lc = (lid & 3) * 2;
    #pragma unroll
    for (int mt = 0; mt < 4; mt++) {
        #pragma unroll
        for (int h2 = 0; h2 < 2; h2++) {
            int row = m0 + wm + mt * 16 + h2 * 8 + lr;
            float* op = av + ((size_t)b * SS + row) * HH;
            #pragma unroll
            for (int nt = 0; nt < 8; nt++) {
                int col = wn + nt * 8 + lc;
                *(float2*)(op + col) = make_float2(acc[mt][nt][h2*2+0], acc[mt][nt][h2*2+1]);
            }
        }
    }
}

// ================= launch =================
extern "C" void kernel_launch(void* const* d_in, const int* in_sizes, int n_in,
                              void* d_out, int out_size)
{
    const float* query  = (const float*)d_in[0];
    const float* value  = (const float*)d_in[2];
    const float* ln_g   = (const float*)d_in[3];
    const float* ln_b   = (const float*)d_in[4];
    const float* W_gate = (const float*)d_in[5];
    const float* b_gate = (const float*)d_in[6];
    const float* W_qk   = (const float*)d_in[7];
    const float* b_qk   = (const float*)d_in[8];
    const float* os_g   = (const float*)d_in[9];
    const float* os_b   = (const float*)d_in[10];
    const float* W_out  = (const float*)d_in[11];
    const float* b_out  = (const float*)d_in[12];

    float* out = (float*)d_out;
    float* att = out + (size_t)ROWS * DD;

    float *p_normed, *p_gate, *p_v, *p_av;
    __nv_bfloat16 *p_vT, *p_qh, *p_ql, *p_kh, *p_kl, *p_atth, *p_attl;
    cudaGetSymbolAddress((void**)&p_normed, g_normed);
    cudaGetSymbolAddress((void**)&p_gate,   g_gate);
    cudaGetSymbolAddress((void**)&p_v,      g_v);
    cudaGetSymbolAddress((void**)&p_av,     g_av);
    cudaGetSymbolAddress((void**)&p_vT,     g_vT);
    cudaGetSymbolAddress((void**)&p_qh,     g_qh);
    cudaGetSymbolAddress((void**)&p_ql,     g_ql);
    cudaGetSymbolAddress((void**)&p_kh,     g_kh);
    cudaGetSymbolAddress((void**)&p_kl,     g_kl);
    cudaGetSymbolAddress((void**)&p_atth,   g_atth);
    cudaGetSymbolAddress((void**)&p_attl,   g_attl);

    cudaFuncSetAttribute(sim_mma,  cudaFuncAttributeMaxDynamicSharedMemorySize, SIM_SMEM);
    cudaFuncSetAttribute(attnv_mma, cudaFuncAttributeMaxDynamicSharedMemorySize, AT_SMEM);

    prep_kernel<<<ROWS, 128>>>(query, ln_g, ln_b, p_normed);
    gemm_small<128, 256, 0><<<ROWS / 64, 256>>>(p_normed, nullptr, W_gate, b_gate,
        nullptr, nullptr, p_gate, nullptr, nullptr, nullptr, nullptr);
    gemm_small<128, 256, 0><<<ROWS / 64, 256>>>(value, nullptr, W_gate, b_gate,
        nullptr, nullptr, p_v, nullptr, nullptr, nullptr, nullptr);
    transpose_kernel<<<dim3(HH / 32, ROWS / 32), dim3(32, 8)>>>(p_v, p_vT);
    gemm_small<128, 128, 1><<<ROWS / 128, 256>>>(p_normed, nullptr, W_qk, b_qk,
        os_g, os_b, nullptr, p_qh, p_ql, p_kh, p_kl);
    sim_mma<<<dim3(SS / 128, SS / 128, BB), 256, SIM_SMEM>>>(p_qh, p_ql, p_kh, p_kl,
        att, p_atth, p_attl);
    attnv_mma<<<dim3(SS / 128, BB), 256, AT_SMEM>>>(p_atth, p_attl, p_vT, p_av);
    gemm_small<256, 128, 2><<<ROWS / 128, 256>>>(p_av, p_gate, W_out, b_out,
        nullptr, nullptr, out, nullptr, nullptr, nullptr, nullptr);
}

// round 4
// speedup vs baseline: 2.8115x; 1.2048x over previous
#include <cuda_runtime.h>
#include <cuda_bf16.h>
#include <math.h>
#include <stdint.h>

#define BB 4
#define SS 4096
#define DD 128
#define HH 256
#define ROWS (BB*SS)   // 16384

typedef __nv_bfloat16 bf16;
typedef __nv_bfloat162 bf162;

// ---------------- scratch (no allocations allowed) ----------------
__device__ bf16 g_nh[ROWS*DD];                // normed hi
__device__ bf16 g_nl[ROWS*DD];                // normed lo
__device__ bf16 g_vih[ROWS*DD];               // value input hi
__device__ bf16 g_vil[ROWS*DD];               // value input lo
__device__ bf16 g_wgh[DD*HH];                 // W_gate^T hi  [256][128]
__device__ bf16 g_wgl[DD*HH];
__device__ bf16 g_wqh[DD*DD];                 // W_qk^T hi    [128][128]
__device__ bf16 g_wql[DD*DD];
__device__ bf16 g_woh[HH*DD];                 // W_out^T hi   [128][256]
__device__ bf16 g_wol[HH*DD];
__device__ float g_gate[ROWS*HH];             // 16 MB f32
__device__ bf16 g_vrow[ROWS*HH];              // v bf16 [seq][256]
__device__ bf16 g_vT[HH*ROWS];                // v^T bf16 [256][16384]
__device__ bf16 g_qh[ROWS*DD];
__device__ bf16 g_ql[ROWS*DD];
__device__ bf16 g_kh[ROWS*DD];
__device__ bf16 g_kl[ROWS*DD];
__device__ bf16 g_avgh[ROWS*HH];              // (att@v)*gate hi
__device__ bf16 g_avgl[ROWS*HH];
__device__ bf16 g_atth[(size_t)ROWS*SS];      // 134 MB
__device__ bf16 g_attl[(size_t)ROWS*SS];      // 134 MB

// ================= PTX helpers (base ISA only) =================
__device__ __forceinline__ uint32_t smem_u32(const void* p) {
    uint32_t a;
    asm("{ .reg .u64 t; cvta.to.shared.u64 t, %1; cvt.u32.u64 %0, t; }" : "=r"(a) : "l"(p));
    return a;
}
__device__ __forceinline__ void cp16(uint32_t s, const void* g) {
    asm volatile("cp.async.cg.shared.global [%0], [%1], 16;" :: "r"(s), "l"(g) : "memory");
}
__device__ __forceinline__ void cp_commit() { asm volatile("cp.async.commit_group;" ::: "memory"); }
template<int N> __device__ __forceinline__ void cp_wait() {
    asm volatile("cp.async.wait_group %0;" :: "n"(N) : "memory");
}
__device__ __forceinline__ void ldm_x4(uint32_t &r0, uint32_t &r1, uint32_t &r2, uint32_t &r3, uint32_t a) {
    asm volatile("ldmatrix.sync.aligned.m8n8.x4.shared.b16 {%0,%1,%2,%3}, [%4];"
        : "=r"(r0), "=r"(r1), "=r"(r2), "=r"(r3) : "r"(a));
}
__device__ __forceinline__ void ldm_x2(uint32_t &r0, uint32_t &r1, uint32_t a) {
    asm volatile("ldmatrix.sync.aligned.m8n8.x2.shared.b16 {%0,%1}, [%2];"
        : "=r"(r0), "=r"(r1) : "r"(a));
}
__device__ __forceinline__ void mma16816(float (&c)[4], const uint32_t (&a)[4], const uint32_t (&b)[2]) {
    asm volatile("mma.sync.aligned.m16n8k16.row.col.f32.bf16.bf16.f32 "
        "{%0,%1,%2,%3}, {%4,%5,%6,%7}, {%8,%9}, {%0,%1,%2,%3};"
        : "+f"(c[0]), "+f"(c[1]), "+f"(c[2]), "+f"(c[3])
        : "r"(a[0]), "r"(a[1]), "r"(a[2]), "r"(a[3]), "r"(b[0]), "r"(b[1]));
}
__device__ __forceinline__ void ldsA(uint32_t (&a)[4], uint32_t base, int mrow, int kt, int lid) {
    int g = lid >> 3, r = lid & 7;
    int row = mrow + ((g & 1) << 3) + r;
    int ch = (kt << 1) + (g >> 1);
    ldm_x4(a[0], a[1], a[2], a[3], base + row * 128 + ((ch ^ (row & 7)) << 4));
}
__device__ __forceinline__ void ldsB(uint32_t (&b)[2], uint32_t base, int nrow, int kt, int lid) {
    int g = (lid >> 3) & 1, r = lid & 7;
    int row = nrow + r;
    int ch = (kt << 1) + g;
    ldm_x2(b[0], b[1], base + row * 128 + ((ch ^ (row & 7)) << 4));
}
template<int NROWS>
__device__ __forceinline__ void load_tile64(uint32_t sbase, const bf16* g, size_t rstride, int tid) {
    #pragma unroll
    for (int i = 0; i < NROWS * 8; i += 256) {
        int idx = i + tid;
        int r = idx >> 3, c = idx & 7;
        cp16(sbase + r * 128 + ((c ^ (r & 7)) << 4), g + (size_t)r * rstride + c * 8);
    }
}
__device__ __forceinline__ float silu_f(float x) { return x / (1.0f + expf(-x)); }
__device__ __forceinline__ void split2(float x, bf16 &h, bf16 &l) {
    h = __float2bfloat16(x);
    l = __float2bfloat16(x - __bfloat162float(h));
}

// ================= kernel 1: rope + layernorm -> bf16 hi/lo =================
__global__ void prep_kernel(const float* __restrict__ q, const float* __restrict__ g,
                            const float* __restrict__ b,
                            bf16* __restrict__ nh, bf16* __restrict__ nl) {
    const int row = blockIdx.x;
    const int d = threadIdx.x;
    const int t = row & (SS - 1);
    float x = q[(size_t)row * DD + d];
    float y = x;
    if (d < 32) {
        int j = d >> 1;
        double dinv = pow(10000.0, -(double)j / 16.0);
        float f = (float)t * (float)dinv;
        float c = cosf(f), s = sinf(f);
        float partner = __shfl_xor_sync(0xffffffffu, x, 1);
        y = (d & 1) ? (x * c + partner * s) : (x * c - partner * s);
    }
    __shared__ float red[4];
    float v = y;
    #pragma unroll
    for (int o2 = 16; o2; o2 >>= 1) v += __shfl_xor_sync(0xffffffffu, v, o2);
    if ((threadIdx.x & 31) == 0) red[threadIdx.x >> 5] = v;
    __syncthreads();
    float mu = (red[0] + red[1] + red[2] + red[3]) * (1.0f / 128.0f);
    float dv = y - mu;
    float v2 = dv * dv;
    __syncthreads();
    #pragma unroll
    for (int o2 = 16; o2; o2 >>= 1) v2 += __shfl_xor_sync(0xffffffffu, v2, o2);
    if ((threadIdx.x & 31) == 0) red[threadIdx.x >> 5] = v2;
    __syncthreads();
    float var = (red[0] + red[1] + red[2] + red[3]) * (1.0f / 128.0f);
    float rs = rsqrtf(var + 1e-5f);
    float out = dv * rs * g[d] + b[d];
    bf16 h, l; split2(out, h, l);
    nh[(size_t)row * DD + d] = h;
    nl[(size_t)row * DD + d] = l;
}

// ================= elementwise f32 -> bf16 hi/lo split =================
__global__ void split_kernel(const float* __restrict__ x, bf16* __restrict__ xh,
                             bf16* __restrict__ xl, int n) {
    int i = blockIdx.x * 256 + threadIdx.x;
    if (i < n) {
        bf16 h, l; split2(x[i], h, l);
        xh[i] = h; xl[i] = l;
    }
}

// ================= weight transpose+split: W[K][N] f32 -> W^T hi/lo [N][K] ==
__global__ void wsplit_kernel(const float* __restrict__ W, bf16* __restrict__ wh,
                              bf16* __restrict__ wl, int K, int N) {
    int k = blockIdx.x * 32 + (threadIdx.x & 31);
    int n = blockIdx.y * 8 + (threadIdx.x >> 5);
    if (k < K && n < N) {
        bf16 h, l; split2(W[(size_t)k * N + n], h, l);
        wh[(size_t)n * K + k] = h;
        wl[(size_t)n * K + k] = l;
    }
}

// ================= bf16 transpose: v[16384][256] -> vT[256][16384] =========
__global__ void transpose_bf16(const bf16* __restrict__ v, bf16* __restrict__ vt) {
    __shared__ bf16 tile[32][33];
    int x = blockIdx.x * 32 + threadIdx.x;   // h
    int y = blockIdx.y * 32 + threadIdx.y;   // seq
    #pragma unroll
    for (int dy = 0; dy < 32; dy += 8)
        tile[threadIdx.y + dy][threadIdx.x] = v[(size_t)(y + dy) * HH + x];
    __syncthreads();
    int xo = blockIdx.y * 32 + threadIdx.x;
    int yo = blockIdx.x * 32 + threadIdx.y;
    #pragma unroll
    for (int dy = 0; dy < 32; dy += 8)
        vt[(size_t)(yo + dy) * ROWS + xo] = tile[threadIdx.x][threadIdx.y + dy];
}

// ================= generic HMMA projection GEMM ==========================
// C[16384,NDIM] = epi(A @ B^T + bias) ; A hi/lo [16384][KDIM], B hi/lo [NDIM][KDIM]
// 3-pass split: Ah*Bh + Ah*Bl + Al*Bh
#define MODE_GATE 0   // silu -> f32 O0f
#define MODE_V    1   // silu -> bf16 O0b
#define MODE_QK   2   // silu, two affines -> qh/ql/kh/kl
#define MODE_OUT  3   // +bias -> f32 O0f

template<int NDIM, int KDIM, int MODE>
__global__ __launch_bounds__(256) void hmma_gemm(
    const bf16* __restrict__ Ah_g, const bf16* __restrict__ Al_g,
    const bf16* __restrict__ Bh_g, const bf16* __restrict__ Bl_g,
    const float* __restrict__ bias, const float* __restrict__ gam,
    const float* __restrict__ bet,
    float* __restrict__ O0f, bf16* __restrict__ O0b,
    bf16* __restrict__ qh, bf16* __restrict__ ql,
    bf16* __restrict__ kh, bf16* __restrict__ kl)
{
    constexpr int NSLAB = KDIM / 64;
    constexpr int BSTG = NDIM * 128;           // bytes per B slab (one of hi/lo)
    constexpr int STG = 32768 + 2 * BSTG;
    constexpr int NT = NDIM / 32;              // 8 (N=256) or 4 (N=128)
    extern __shared__ __align__(128) char smem[];
    const uint32_t sb = smem_u32(smem);
    const int tid = threadIdx.x, wid = tid >> 5, lid = tid & 31;
    const int m0 = blockIdx.x * 128;
    const bf16* Ahp = Ah_g + (size_t)m0 * KDIM;
    const bf16* Alp = Al_g + (size_t)m0 * KDIM;

    const int wm = (wid >> 2) * 64;
    const int wn = (wid & 3) * (NDIM / 4);
    float acc[4][NT][4];
    #pragma unroll
    for (int i = 0; i < 4; i++)
        #pragma unroll
        for (int j = 0; j < NT; j++)
            #pragma unroll
            for (int e = 0; e < 4; e++) acc[i][j][e] = 0.f;

    auto load_slab = [&](int s, uint32_t base) {
        load_tile64<128>(base,          Ahp + s * 64, KDIM, tid);
        load_tile64<128>(base + 16384,  Alp + s * 64, KDIM, tid);
        load_tile64<NDIM>(base + 32768, Bh_g + s * 64, KDIM, tid);
        load_tile64<NDIM>(base + 32768 + BSTG, Bl_g + s * 64, KDIM, tid);
        cp_commit();
    };
    auto compute = [&](uint32_t base) {
        const uint32_t Ah = base, Al = base + 16384;
        const uint32_t Bh = base + 32768, Bl = base + 32768 + BSTG;
        #pragma unroll
        for (int kt = 0; kt < 4; kt++) {
            uint32_t bh[NT][2], bl[NT][2], af[4][4];
            #pragma unroll
            for (int nt = 0; nt < NT; nt++) { ldsB(bh[nt], Bh, wn + nt*8, kt, lid); ldsB(bl[nt], Bl, wn + nt*8, kt, lid); }
            #pragma unroll
            for (int mt = 0; mt < 4; mt++) ldsA(af[mt], Ah, wm + mt*16, kt, lid);
            #pragma unroll
            for (int mt = 0; mt < 4; mt++)
                #pragma unroll
                for (int nt = 0; nt < NT; nt++) mma16816(acc[mt][nt], af[mt], bh[nt]);
            #pragma unroll
            for (int mt = 0; mt < 4; mt++)
                #pragma unroll
                for (int nt = 0; nt < NT; nt++) mma16816(acc[mt][nt], af[mt], bl[nt]);
            #pragma unroll
            for (int mt = 0; mt < 4; mt++) ldsA(af[mt], Al, wm + mt*16, kt, lid);
            #pragma unroll
            for (int mt = 0; mt < 4; mt++)
                #pragma unroll
                for (int nt = 0; nt < NT; nt++) mma16816(acc[mt][nt], af[mt], bh[nt]);
        }
    };

    load_slab(0, sb);
    if (NSLAB > 1) load_slab(1, sb + STG);
    #pragma unroll
    for (int j = 0; j < NSLAB; j++) {
        if (j + 1 < NSLAB) cp_wait<1>(); else cp_wait<0>();
        __syncthreads();
        compute(sb + (j & 1) * STG);
        if (j + 2 < NSLAB) { __syncthreads(); load_slab(j + 2, sb + (j & 1) * STG); }
    }

    const int lr = lid >> 2, lc = (lid & 3) * 2;
    #pragma unroll
    for (int mt = 0; mt < 4; mt++) {
        #pragma unroll
        for (int h2 = 0; h2 < 2; h2++) {
            const int row = m0 + wm + mt * 16 + h2 * 8 + lr;
            #pragma unroll
            for (int nt = 0; nt < NT; nt++) {
                const int col = wn + nt * 8 + lc;
                float x0 = acc[mt][nt][h2*2+0] + bias[col];
                float x1 = acc[mt][nt][h2*2+1] + bias[col+1];
                if (MODE == MODE_GATE) {
                    *(float2*)(O0f + (size_t)row * NDIM + col) = make_float2(silu_f(x0), silu_f(x1));
                } else if (MODE == MODE_V) {
                    bf162 p; p.x = __float2bfloat16(silu_f(x0)); p.y = __float2bfloat16(silu_f(x1));
                    *(bf162*)(O0b + (size_t)row * NDIM + col) = p;
                } else if (MODE == MODE_QK) {
                    float y0 = silu_f(x0), y1 = silu_f(x1);
                    float q0 = y0 * gam[col] + bet[col], q1 = y1 * gam[col+1] + bet[col+1];
                    float k0 = y0 * gam[NDIM+col] + bet[NDIM+col], k1 = y1 * gam[NDIM+col+1] + bet[NDIM+col+1];
                    bf162 hp, lp;
                    split2(q0, hp.x, lp.x); split2(q1, hp.y, lp.y);
                    *(bf162*)(qh + (size_t)row * NDIM + col) = hp;
                    *(bf162*)(ql + (size_t)row * NDIM + col) = lp;
                    split2(k0, hp.x, lp.x); split2(k1, hp.y, lp.y);
                    *(bf162*)(kh + (size_t)row * NDIM + col) = hp;
                    *(bf162*)(kl + (size_t)row * NDIM + col) = lp;
                } else {
                    *(float2*)(O0f + (size_t)row * NDIM + col) = make_float2(x0, x1);
                }
            }
        }
    }
}

// ================= big GEMM 1: att = relu(q@k^T/S)^2  (HMMA bf16 3-pass) ===
#define SIM_STG 65536
#define SIM_SMEM (2*SIM_STG)

__global__ __launch_bounds__(256) void sim_mma(
    const bf16* __restrict__ qh_g, const bf16* __restrict__ ql_g,
    const bf16* __restrict__ kh_g, const bf16* __restrict__ kl_g,
    float* __restrict__ att, bf16* __restrict__ atth, bf16* __restrict__ attl)
{
    extern __shared__ __align__(128) char smem[];
    const uint32_t sb = smem_u32(smem);
    const int tid = threadIdx.x, wid = tid >> 5, lid = tid & 31;
    const int b = blockIdx.z, m0 = blockIdx.y * 128, n0 = blockIdx.x * 128;
    const bf16* qhp = qh_g + ((size_t)b * SS + m0) * DD;
    const bf16* qlp = ql_g + ((size_t)b * SS + m0) * DD;
    const bf16* khp = kh_g + ((size_t)b * SS + n0) * DD;
    const bf16* klp = kl_g + ((size_t)b * SS + n0) * DD;

    const int wm = (wid >> 2) * 64, wn = (wid & 3) * 32;
    float acc[4][4][4];
    #pragma unroll
    for (int i = 0; i < 4; i++)
        #pragma unroll
        for (int j = 0; j < 4; j++)
            #pragma unroll
            for (int e = 0; e < 4; e++) acc[i][j][e] = 0.f;

    auto load_half = [&](int h, uint32_t base) {
        load_tile64<128>(base,         qhp + h * 64, DD, tid);
        load_tile64<128>(base + 16384, qlp + h * 64, DD, tid);
        load_tile64<128>(base + 32768, khp + h * 64, DD, tid);
        load_tile64<128>(base + 49152, klp + h * 64, DD, tid);
        cp_commit();
    };
    auto compute = [&](uint32_t base) {
        const uint32_t Ah = base, Al = base + 16384, Bh = base + 32768, Bl = base + 49152;
        #pragma unroll
        for (int kt = 0; kt < 4; kt++) {
            uint32_t bh[4][2], bl[4][2], ah[4][4], al[4][4];
            #pragma unroll
            for (int nt = 0; nt < 4; nt++) { ldsB(bh[nt], Bh, wn + nt*8, kt, lid); ldsB(bl[nt], Bl, wn + nt*8, kt, lid); }
            #pragma unroll
            for (int mt = 0; mt < 4; mt++) ldsA(ah[mt], Ah, wm + mt*16, kt, lid);
            #pragma unroll
            for (int mt = 0; mt < 4; mt++)
                #pragma unroll
                for (int nt = 0; nt < 4; nt++) mma16816(acc[mt][nt], ah[mt], bh[nt]);
            #pragma unroll
            for (int mt = 0; mt < 4; mt++)
                #pragma unroll
                for (int nt = 0; nt < 4; nt++) mma16816(acc[mt][nt], ah[mt], bl[nt]);
            #pragma unroll
            for (int mt = 0; mt < 4; mt++) ldsA(al[mt], Al, wm + mt*16, kt, lid);
            #pragma unroll
            for (int mt = 0; mt < 4; mt++)
                #pragma unroll
                for (int nt = 0; nt < 4; nt++) mma16816(acc[mt][nt], al[mt], bh[nt]);
        }
    };

    load_half(0, sb);
    load_half(1, sb + SIM_STG);
    cp_wait<1>(); __syncthreads();
    compute(sb);
    cp_wait<0>(); __syncthreads();
    compute(sb + SIM_STG);

    const float invS = 1.0f / (float)SS;
    const int lr = lid >> 2, lc = (lid & 3) * 2;
    float* attb = att + (size_t)b * SS * SS;
    bf16* hib = atth + (size_t)b * SS * SS;
    bf16* lob = attl + (size_t)b * SS * SS;
    #pragma unroll
    for (int mt = 0; mt < 4; mt++) {
        #pragma unroll
        for (int h2 = 0; h2 < 2; h2++) {
            int row = m0 + wm + mt * 16 + h2 * 8 + lr;
            size_t ro = (size_t)row * SS;
            #pragma unroll
            for (int nt = 0; nt < 4; nt++) {
                int col = n0 + wn + nt * 8 + lc;
                float s0 = fmaxf(acc[mt][nt][h2*2+0] * invS, 0.f);
                float s1 = fmaxf(acc[mt][nt][h2*2+1] * invS, 0.f);
                float a0 = s0 * s0, a1 = s1 * s1;
                *(float2*)(attb + ro + col) = make_float2(a0, a1);
                bf162 hp, lp;
                split2(a0, hp.x, lp.x); split2(a1, hp.y, lp.y);
                *(bf162*)(hib + ro + col) = hp;
                *(bf162*)(lob + ro + col) = lp;
            }
        }
    }
}

// ================= big GEMM 2: av = att @ v, fused *gate -> hi/lo ==========
#define AT_STG 65536
#define AT_SMEM (3*AT_STG)
#define AT_NS 64

__global__ __launch_bounds__(256) void attnv_mma(
    const bf16* __restrict__ atth, const bf16* __restrict__ attl,
    const bf16* __restrict__ vt, const float* __restrict__ gate,
    bf16* __restrict__ avgh, bf16* __restrict__ avgl)
{
    extern __shared__ __align__(128) char smem[];
    const uint32_t sb = smem_u32(smem);
    const int tid = threadIdx.x, wid = tid >> 5, lid = tid & 31;
    const int b = blockIdx.y, m0 = blockIdx.x * 128;
    const bf16* ahp = atth + (size_t)b * SS * SS + (size_t)m0 * SS;
    const bf16* alp = attl + (size_t)b * SS * SS + (size_t)m0 * SS;
    const bf16* vp  = vt + (size_t)b * SS;

    const int wm = (wid >> 2) * 64, wn = (wid & 3) * 64;
    float acc[4][8][4];
    #pragma unroll
    for (int i = 0; i < 4; i++)
        #pragma unroll
        for (int j = 0; j < 8; j++)
            #pragma unroll
            for (int e = 0; e < 4; e++) acc[i][j][e] = 0.f;

    auto load_slab = [&](int j, int s) {
        uint32_t base = sb + s * AT_STG;
        load_tile64<128>(base,         ahp + j * 64, SS, tid);
        load_tile64<128>(base + 16384, alp + j * 64, SS, tid);
        load_tile64<256>(base + 32768, vp + j * 64, ROWS, tid);
        cp_commit();
    };
    auto compute = [&](int s) {
        uint32_t base = sb + s * AT_STG;
        const uint32_t Ah = base, Al = base + 16384, Bv = base + 32768;
        #pragma unroll
        for (int kt = 0; kt < 4; kt++) {
            uint32_t bf[8][2];
            #pragma unroll
            for (int nt = 0; nt < 8; nt++) ldsB(bf[nt], Bv, wn + nt*8, kt, lid);
            uint32_t af[4][4];
            #pragma unroll
            for (int mt = 0; mt < 4; mt++) ldsA(af[mt], Ah, wm + mt*16, kt, lid);
            #pragma unroll
            for (int mt = 0; mt < 4; mt++)
                #pragma unroll
                for (int nt = 0; nt < 8; nt++) mma16816(acc[mt][nt], af[mt], bf[nt]);
            #pragma unroll
            for (int mt = 0; mt < 4; mt++) ldsA(af[mt], Al, wm + mt*16, kt, lid);
            #pragma unroll
            for (int mt = 0; mt < 4; mt++)
                #pragma unroll
                for (int nt = 0; nt < 8; nt++) mma16816(acc[mt][nt], af[mt], bf[nt]);
        }
    };

    load_slab(0, 0);
    load_slab(1, 1);
    for (int j = 0; j < AT_NS; j++) {
        if (j + 1 < AT_NS) cp_wait<1>(); else cp_wait<0>();
        __syncthreads();
        if (j + 2 < AT_NS) load_slab(j + 2, (j + 2) % 3);
        compute(j % 3);
    }

    const int lr = lid >> 2, lc = (lid & 3) * 2;
    #pragma unroll
    for (int mt = 0; mt < 4; mt++) {
        #pragma unroll
        for (int h2 = 0; h2 < 2; h2++) {
            size_t grow = (size_t)b * SS + m0 + wm + mt * 16 + h2 * 8 + lr;
            const float* gp = gate + grow * HH;
            bf16* hp_ = avgh + grow * HH;
            bf16* lp_ = avgl + grow * HH;
            #pragma unroll
            for (int nt = 0; nt < 8; nt++) {
                int col = wn + nt * 8 + lc;
                float2 g2 = *(const float2*)(gp + col);
                float o0 = acc[mt][nt][h2*2+0] * g2.x;
                float o1 = acc[mt][nt][h2*2+1] * g2.y;
                bf162 hh, ll;
                split2(o0, hh.x, ll.x); split2(o1, hh.y, ll.y);
                *(bf162*)(hp_ + col) = hh;
                *(bf162*)(lp_ + col) = ll;
            }
        }
    }
}

// ================= launch =================
extern "C" void kernel_launch(void* const* d_in, const int* in_sizes, int n_in,
                              void* d_out, int out_size)
{
    const float* query  = (const float*)d_in[0];
    const float* value  = (const float*)d_in[2];
    const float* ln_g   = (const float*)d_in[3];
    const float* ln_b   = (const float*)d_in[4];
    const float* W_gate = (const float*)d_in[5];
    const float* b_gate = (const float*)d_in[6];
    const float* W_qk   = (const float*)d_in[7];
    const float* b_qk   = (const float*)d_in[8];
    const float* os_g   = (const float*)d_in[9];
    const float* os_b   = (const float*)d_in[10];
    const float* W_out  = (const float*)d_in[11];
    const float* b_out  = (const float*)d_in[12];

    float* out = (float*)d_out;
    float* att = out + (size_t)ROWS * DD;

    bf16 *p_nh, *p_nl, *p_vih, *p_vil, *p_wgh, *p_wgl, *p_wqh, *p_wql, *p_woh, *p_wol;
    bf16 *p_vrow, *p_vT, *p_qh, *p_ql, *p_kh, *p_kl, *p_avgh, *p_avgl, *p_atth, *p_attl;
    float *p_gate;
    cudaGetSymbolAddress((void**)&p_nh, g_nh);
    cudaGetSymbolAddress((void**)&p_nl, g_nl);
    cudaGetSymbolAddress((void**)&p_vih, g_vih);
    cudaGetSymbolAddress((void**)&p_vil, g_vil);
    cudaGetSymbolAddress((void**)&p_wgh, g_wgh);
    cudaGetSymbolAddress((void**)&p_wgl, g_wgl);
    cudaGetSymbolAddress((void**)&p_wqh, g_wqh);
    cudaGetSymbolAddress((void**)&p_wql, g_wql);
    cudaGetSymbolAddress((void**)&p_woh, g_woh);
    cudaGetSymbolAddress((void**)&p_wol, g_wol);
    cudaGetSymbolAddress((void**)&p_gate, g_gate);
    cudaGetSymbolAddress((void**)&p_vrow, g_vrow);
    cudaGetSymbolAddress((void**)&p_vT, g_vT);
    cudaGetSymbolAddress((void**)&p_qh, g_qh);
    cudaGetSymbolAddress((void**)&p_ql, g_ql);
    cudaGetSymbolAddress((void**)&p_kh, g_kh);
    cudaGetSymbolAddress((void**)&p_kl, g_kl);
    cudaGetSymbolAddress((void**)&p_avgh, g_avgh);
    cudaGetSymbolAddress((void**)&p_avgl, g_avgl);
    cudaGetSymbolAddress((void**)&p_atth, g_atth);
    cudaGetSymbolAddress((void**)&p_attl, g_attl);

    cudaFuncSetAttribute(sim_mma,  cudaFuncAttributeMaxDynamicSharedMemorySize, SIM_SMEM);
    cudaFuncSetAttribute(attnv_mma, cudaFuncAttributeMaxDynamicSharedMemorySize, AT_SMEM);
    cudaFuncSetAttribute((const void*)hmma_gemm<256,128,MODE_GATE>, cudaFuncAttributeMaxDynamicSharedMemorySize, 2*(32768+2*256*128));
    cudaFuncSetAttribute((const void*)hmma_gemm<256,128,MODE_V>,    cudaFuncAttributeMaxDynamicSharedMemorySize, 2*(32768+2*256*128));
    cudaFuncSetAttribute((const void*)hmma_gemm<128,128,MODE_QK>,   cudaFuncAttributeMaxDynamicSharedMemorySize, 2*(32768+2*128*128));
    cudaFuncSetAttribute((const void*)hmma_gemm<128,256,MODE_OUT>,  cudaFuncAttributeMaxDynamicSharedMemorySize, 2*(32768+2*128*128));

    // prep + splits
    prep_kernel<<<ROWS, 128>>>(query, ln_g, ln_b, p_nh, p_nl);
    split_kernel<<<(ROWS*DD + 255)/256, 256>>>(value, p_vih, p_vil, ROWS*DD);
    wsplit_kernel<<<dim3(4, 32), 256>>>(W_gate, p_wgh, p_wgl, DD, HH);
    wsplit_kernel<<<dim3(4, 16), 256>>>(W_qk,   p_wqh, p_wql, DD, DD);
    wsplit_kernel<<<dim3(8, 16), 256>>>(W_out,  p_woh, p_wol, HH, DD);

    // projections (HMMA)
    hmma_gemm<256,128,MODE_GATE><<<128, 256, 2*(32768+2*256*128)>>>(
        p_nh, p_nl, p_wgh, p_wgl, b_gate, nullptr, nullptr,
        p_gate, nullptr, nullptr, nullptr, nullptr, nullptr);
    hmma_gemm<256,128,MODE_V><<<128, 256, 2*(32768+2*256*128)>>>(
        p_vih, p_vil, p_wgh, p_wgl, b_gate, nullptr, nullptr,
        nullptr, p_vrow, nullptr, nullptr, nullptr, nullptr);
    hmma_gemm<128,128,MODE_QK><<<128, 256, 2*(32768+2*128*128)>>>(
        p_nh, p_nl, p_wqh, p_wql, b_qk, os_g, os_b,
        nullptr, nullptr, p_qh, p_ql, p_kh, p_kl);
    transpose_bf16<<<dim3(HH/32, ROWS/32), dim3(32, 8)>>>(p_vrow, p_vT);

    // attention
    sim_mma<<<dim3(SS/128, SS/128, BB), 256, SIM_SMEM>>>(p_qh, p_ql, p_kh, p_kl,
        att, p_atth, p_attl);
    attnv_mma<<<dim3(SS/128, BB), 256, AT_SMEM>>>(p_atth, p_attl, p_vT, p_gate,
        p_avgh, p_avgl);

    // output projection
    hmma_gemm<128,256,MODE_OUT><<<128, 256, 2*(32768+2*128*128)>>>(
        p_avgh, p_avgl, p_woh, p_wol, b_out, nullptr, nullptr,
        out, nullptr, nullptr, nullptr, nullptr, nullptr);
}

// round 5
// speedup vs baseline: 3.0665x; 1.0907x over previous
#include <cuda_runtime.h>
#include <cuda_bf16.h>
#include <math.h>
#include <stdint.h>

#define BB 4
#define SS 4096
#define DD 128
#define HH 256
#define ROWS (BB*SS)   // 16384

typedef __nv_bfloat16 bf16;
typedef __nv_bfloat162 bf162;

// ---------------- scratch (no allocations allowed) ----------------
__device__ bf16 g_nh[ROWS*DD];                // normed hi
__device__ bf16 g_nl[ROWS*DD];                // normed lo
__device__ bf16 g_vih[ROWS*DD];               // value input hi
__device__ bf16 g_vil[ROWS*DD];               // value input lo
__device__ bf16 g_wgh[DD*HH];                 // W_gate^T hi  [256][128]
__device__ bf16 g_wgl[DD*HH];
__device__ bf16 g_wqh[DD*DD];                 // W_qk^T hi    [128][128]
__device__ bf16 g_wql[DD*DD];
__device__ bf16 g_woh[HH*DD];                 // W_out^T hi   [128][256]
__device__ bf16 g_wol[HH*DD];
__device__ float g_gate[ROWS*HH];             // 16 MB f32
__device__ bf16 g_vrh[ROWS*HH];               // v hi [seq][256]
__device__ bf16 g_vrl[ROWS*HH];               // v lo
__device__ bf16 g_vTh[HH*ROWS];               // v^T hi [256][16384]
__device__ bf16 g_vTl[HH*ROWS];
__device__ bf16 g_qh[ROWS*DD];
__device__ bf16 g_ql[ROWS*DD];
__device__ bf16 g_kh[ROWS*DD];
__device__ bf16 g_kl[ROWS*DD];
__device__ bf16 g_avgh[ROWS*HH];              // (att@v)*gate hi
__device__ bf16 g_avgl[ROWS*HH];
__device__ bf16 g_atth[(size_t)ROWS*SS];      // 134 MB

// ================= PTX helpers (base ISA only) =================
__device__ __forceinline__ uint32_t smem_u32(const void* p) {
    uint32_t a;
    asm("{ .reg .u64 t; cvta.to.shared.u64 t, %1; cvt.u32.u64 %0, t; }" : "=r"(a) : "l"(p));
    return a;
}
__device__ __forceinline__ void cp16(uint32_t s, const void* g) {
    asm volatile("cp.async.cg.shared.global [%0], [%1], 16;" :: "r"(s), "l"(g) : "memory");
}
__device__ __forceinline__ void cp_commit() { asm volatile("cp.async.commit_group;" ::: "memory"); }
template<int N> __device__ __forceinline__ void cp_wait() {
    asm volatile("cp.async.wait_group %0;" :: "n"(N) : "memory");
}
__device__ __forceinline__ void ldm_x4(uint32_t &r0, uint32_t &r1, uint32_t &r2, uint32_t &r3, uint32_t a) {
    asm volatile("ldmatrix.sync.aligned.m8n8.x4.shared.b16 {%0,%1,%2,%3}, [%4];"
        : "=r"(r0), "=r"(r1), "=r"(r2), "=r"(r3) : "r"(a));
}
__device__ __forceinline__ void ldm_x2(uint32_t &r0, uint32_t &r1, uint32_t a) {
    asm volatile("ldmatrix.sync.aligned.m8n8.x2.shared.b16 {%0,%1}, [%2];"
        : "=r"(r0), "=r"(r1) : "r"(a));
}
__device__ __forceinline__ void mma16816(float (&c)[4], const uint32_t (&a)[4], const uint32_t (&b)[2]) {
    asm volatile("mma.sync.aligned.m16n8k16.row.col.f32.bf16.bf16.f32 "
        "{%0,%1,%2,%3}, {%4,%5,%6,%7}, {%8,%9}, {%0,%1,%2,%3};"
        : "+f"(c[0]), "+f"(c[1]), "+f"(c[2]), "+f"(c[3])
        : "r"(a[0]), "r"(a[1]), "r"(a[2]), "r"(a[3]), "r"(b[0]), "r"(b[1]));
}
__device__ __forceinline__ void ldsA(uint32_t (&a)[4], uint32_t base, int mrow, int kt, int lid) {
    int g = lid >> 3, r = lid & 7;
    int row = mrow + ((g & 1) << 3) + r;
    int ch = (kt << 1) + (g >> 1);
    ldm_x4(a[0], a[1], a[2], a[3], base + row * 128 + ((ch ^ (row & 7)) << 4));
}
__device__ __forceinline__ void ldsB(uint32_t (&b)[2], uint32_t base, int nrow, int kt, int lid) {
    int g = (lid >> 3) & 1, r = lid & 7;
    int row = nrow + r;
    int ch = (kt << 1) + g;
    ldm_x2(b[0], b[1], base + row * 128 + ((ch ^ (row & 7)) << 4));
}
template<int NROWS>
__device__ __forceinline__ void load_tile64(uint32_t sbase, const bf16* g, size_t rstride, int tid) {
    #pragma unroll
    for (int i = 0; i < NROWS * 8; i += 256) {
        int idx = i + tid;
        int r = idx >> 3, c = idx & 7;
        cp16(sbase + r * 128 + ((c ^ (r & 7)) << 4), g + (size_t)r * rstride + c * 8);
    }
}
__device__ __forceinline__ float silu_f(float x) { return x / (1.0f + expf(-x)); }
__device__ __forceinline__ void split2(float x, bf16 &h, bf16 &l) {
    h = __float2bfloat16(x);
    l = __float2bfloat16(x - __bfloat162float(h));
}

// ================= kernel 1: rope + layernorm -> bf16 hi/lo =================
__global__ void prep_kernel(const float* __restrict__ q, const float* __restrict__ g,
                            const float* __restrict__ b,
                            bf16* __restrict__ nh, bf16* __restrict__ nl) {
    const int row = blockIdx.x;
    const int d = threadIdx.x;
    const int t = row & (SS - 1);
    float x = q[(size_t)row * DD + d];
    float y = x;
    if (d < 32) {
        int j = d >> 1;
        double dinv = pow(10000.0, -(double)j / 16.0);
        float f = (float)t * (float)dinv;
        float c = cosf(f), s = sinf(f);
        float partner = __shfl_xor_sync(0xffffffffu, x, 1);
        y = (d & 1) ? (x * c + partner * s) : (x * c - partner * s);
    }
    __shared__ float red[4];
    float v = y;
    #pragma unroll
    for (int o2 = 16; o2; o2 >>= 1) v += __shfl_xor_sync(0xffffffffu, v, o2);
    if ((threadIdx.x & 31) == 0) red[threadIdx.x >> 5] = v;
    __syncthreads();
    float mu = (red[0] + red[1] + red[2] + red[3]) * (1.0f / 128.0f);
    float dv = y - mu;
    float v2 = dv * dv;
    __syncthreads();
    #pragma unroll
    for (int o2 = 16; o2; o2 >>= 1) v2 += __shfl_xor_sync(0xffffffffu, v2, o2);
    if ((threadIdx.x & 31) == 0) red[threadIdx.x >> 5] = v2;
    __syncthreads();
    float var = (red[0] + red[1] + red[2] + red[3]) * (1.0f / 128.0f);
    float rs = rsqrtf(var + 1e-5f);
    float out = dv * rs * g[d] + b[d];
    bf16 h, l; split2(out, h, l);
    nh[(size_t)row * DD + d] = h;
    nl[(size_t)row * DD + d] = l;
}

// ================= elementwise f32 -> bf16 hi/lo split =================
__global__ void split_kernel(const float* __restrict__ x, bf16* __restrict__ xh,
                             bf16* __restrict__ xl, int n) {
    int i = blockIdx.x * 256 + threadIdx.x;
    if (i < n) {
        bf16 h, l; split2(x[i], h, l);
        xh[i] = h; xl[i] = l;
    }
}

// ================= all weights transpose+split in ONE launch =================
// regions: 0: W_gate [128][256] -> [256][128]; 1: W_qk [128][128]; 2: W_out [256][128] -> [128][256]
__global__ void wsplit_all(const float* __restrict__ Wg, const float* __restrict__ Wq,
                           const float* __restrict__ Wo,
                           bf16* __restrict__ wgh, bf16* __restrict__ wgl,
                           bf16* __restrict__ wqh, bf16* __restrict__ wql,
                           bf16* __restrict__ woh, bf16* __restrict__ wol) {
    int i = blockIdx.x * 256 + threadIdx.x;   // 0..81919
    const float* W; bf16 *wh, *wl; int K, N, off;
    if (i < 32768)       { W = Wg; wh = wgh; wl = wgl; K = 128; N = 256; off = i; }
    else if (i < 49152)  { W = Wq; wh = wqh; wl = wql; K = 128; N = 128; off = i - 32768; }
    else if (i < 81920)  { W = Wo; wh = woh; wl = wol; K = 256; N = 128; off = i - 49152; }
    else return;
    int k = off / N, n = off % N;
    bf16 h, l; split2(W[(size_t)k * N + n], h, l);
    wh[(size_t)n * K + k] = h;
    wl[(size_t)n * K + k] = l;
}

// ================= bf16 transpose (hi & lo via z): [16384][256]->[256][16384]
__global__ void transpose2(const bf16* __restrict__ vh, const bf16* __restrict__ vl,
                           bf16* __restrict__ vth, bf16* __restrict__ vtl) {
    const bf16* in = blockIdx.z ? vl : vh;
    bf16* out = blockIdx.z ? vtl : vth;
    __shared__ bf16 tile[32][33];
    int x = blockIdx.x * 32 + threadIdx.x;
    int y = blockIdx.y * 32 + threadIdx.y;
    #pragma unroll
    for (int dy = 0; dy < 32; dy += 8)
        tile[threadIdx.y + dy][threadIdx.x] = in[(size_t)(y + dy) * HH + x];
    __syncthreads();
    int xo = blockIdx.y * 32 + threadIdx.x;
    int yo = blockIdx.x * 32 + threadIdx.y;
    #pragma unroll
    for (int dy = 0; dy < 32; dy += 8)
        out[(size_t)(yo + dy) * ROWS + xo] = tile[threadIdx.x][threadIdx.y + dy];
}

// ================= generic HMMA projection GEMM ==========================
#define MODE_GATE 0   // silu -> f32 O0f
#define MODE_V    1   // silu -> bf16 hi/lo (qh=hi, ql=lo)
#define MODE_QK   2   // silu, two affines -> qh/ql/kh/kl
#define MODE_OUT  3   // +bias -> f32 O0f

template<int NDIM, int KDIM, int MODE>
__global__ __launch_bounds__(256) void hmma_gemm(
    const bf16* __restrict__ Ah_g, const bf16* __restrict__ Al_g,
    const bf16* __restrict__ Bh_g, const bf16* __restrict__ Bl_g,
    const float* __restrict__ bias, const float* __restrict__ gam,
    const float* __restrict__ bet,
    float* __restrict__ O0f,
    bf16* __restrict__ qh, bf16* __restrict__ ql,
    bf16* __restrict__ kh, bf16* __restrict__ kl)
{
    constexpr int NSLAB = KDIM / 64;
    constexpr int BSTG = NDIM * 128;
    constexpr int STG = 32768 + 2 * BSTG;
    constexpr int NT = NDIM / 32;
    extern __shared__ __align__(128) char smem[];
    const uint32_t sb = smem_u32(smem);
    const int tid = threadIdx.x, wid = tid >> 5, lid = tid & 31;
    const int m0 = blockIdx.x * 128;
    const bf16* Ahp = Ah_g + (size_t)m0 * KDIM;
    const bf16* Alp = Al_g + (size_t)m0 * KDIM;

    const int wm = (wid >> 2) * 64;
    const int wn = (wid & 3) * (NDIM / 4);
    float acc[4][NT][4];
    #pragma unroll
    for (int i = 0; i < 4; i++)
        #pragma unroll
        for (int j = 0; j < NT; j++)
            #pragma unroll
            for (int e = 0; e < 4; e++) acc[i][j][e] = 0.f;

    auto load_slab = [&](int s, uint32_t base) {
        load_tile64<128>(base,          Ahp + s * 64, KDIM, tid);
        load_tile64<128>(base + 16384,  Alp + s * 64, KDIM, tid);
        load_tile64<NDIM>(base + 32768, Bh_g + s * 64, KDIM, tid);
        load_tile64<NDIM>(base + 32768 + BSTG, Bl_g + s * 64, KDIM, tid);
        cp_commit();
    };
    auto compute = [&](uint32_t base) {
        const uint32_t Ah = base, Al = base + 16384;
        const uint32_t Bh = base + 32768, Bl = base + 32768 + BSTG;
        #pragma unroll
        for (int kt = 0; kt < 4; kt++) {
            uint32_t bh[NT][2], bl[NT][2], af[4][4];
            #pragma unroll
            for (int nt = 0; nt < NT; nt++) { ldsB(bh[nt], Bh, wn + nt*8, kt, lid); ldsB(bl[nt], Bl, wn + nt*8, kt, lid); }
            #pragma unroll
            for (int mt = 0; mt < 4; mt++) ldsA(af[mt], Ah, wm + mt*16, kt, lid);
            #pragma unroll
            for (int mt = 0; mt < 4; mt++)
                #pragma unroll
                for (int nt = 0; nt < NT; nt++) mma16816(acc[mt][nt], af[mt], bh[nt]);
            #pragma unroll
            for (int mt = 0; mt < 4; mt++)
                #pragma unroll
                for (int nt = 0; nt < NT; nt++) mma16816(acc[mt][nt], af[mt], bl[nt]);
            #pragma unroll
            for (int mt = 0; mt < 4; mt++) ldsA(af[mt], Al, wm + mt*16, kt, lid);
            #pragma unroll
            for (int mt = 0; mt < 4; mt++)
                #pragma unroll
                for (int nt = 0; nt < NT; nt++) mma16816(acc[mt][nt], af[mt], bh[nt]);
        }
    };

    load_slab(0, sb);
    if (NSLAB > 1) load_slab(1, sb + STG);
    #pragma unroll
    for (int j = 0; j < NSLAB; j++) {
        if (j + 1 < NSLAB) cp_wait<1>(); else cp_wait<0>();
        __syncthreads();
        compute(sb + (j & 1) * STG);
        if (j + 2 < NSLAB) { __syncthreads(); load_slab(j + 2, sb + (j & 1) * STG); }
    }

    const int lr = lid >> 2, lc = (lid & 3) * 2;
    #pragma unroll
    for (int mt = 0; mt < 4; mt++) {
        #pragma unroll
        for (int h2 = 0; h2 < 2; h2++) {
            const int row = m0 + wm + mt * 16 + h2 * 8 + lr;
            #pragma unroll
            for (int nt = 0; nt < NT; nt++) {
                const int col = wn + nt * 8 + lc;
                float x0 = acc[mt][nt][h2*2+0] + bias[col];
                float x1 = acc[mt][nt][h2*2+1] + bias[col+1];
                if (MODE == MODE_GATE) {
                    *(float2*)(O0f + (size_t)row * NDIM + col) = make_float2(silu_f(x0), silu_f(x1));
                } else if (MODE == MODE_V) {
                    bf162 hp, lp;
                    split2(silu_f(x0), hp.x, lp.x); split2(silu_f(x1), hp.y, lp.y);
                    *(bf162*)(qh + (size_t)row * NDIM + col) = hp;
                    *(bf162*)(ql + (size_t)row * NDIM + col) = lp;
                } else if (MODE == MODE_QK) {
                    float y0 = silu_f(x0), y1 = silu_f(x1);
                    float q0 = y0 * gam[col] + bet[col], q1 = y1 * gam[col+1] + bet[col+1];
                    float k0 = y0 * gam[NDIM+col] + bet[NDIM+col], k1 = y1 * gam[NDIM+col+1] + bet[NDIM+col+1];
                    bf162 hp, lp;
                    split2(q0, hp.x, lp.x); split2(q1, hp.y, lp.y);
                    *(bf162*)(qh + (size_t)row * NDIM + col) = hp;
                    *(bf162*)(ql + (size_t)row * NDIM + col) = lp;
                    split2(k0, hp.x, lp.x); split2(k1, hp.y, lp.y);
                    *(bf162*)(kh + (size_t)row * NDIM + col) = hp;
                    *(bf162*)(kl + (size_t)row * NDIM + col) = lp;
                } else {
                    *(float2*)(O0f + (size_t)row * NDIM + col) = make_float2(x0, x1);
                }
            }
        }
    }
}

// ================= big GEMM 1: att = relu(q@k^T/S)^2  (HMMA 3-pass, 128x256)
#define SIM_STG 98304   // Ah 16K | Al 16K | Bh 32K | Bl 32K
#define SIM_SMEM (2*SIM_STG)

__global__ __launch_bounds__(256) void sim_mma(
    const bf16* __restrict__ qh_g, const bf16* __restrict__ ql_g,
    const bf16* __restrict__ kh_g, const bf16* __restrict__ kl_g,
    float* __restrict__ att, bf16* __restrict__ atth)
{
    extern __shared__ __align__(128) char smem[];
    const uint32_t sb = smem_u32(smem);
    const int tid = threadIdx.x, wid = tid >> 5, lid = tid & 31;
    const int b = blockIdx.z, m0 = blockIdx.y * 128, n0 = blockIdx.x * 256;
    const bf16* qhp = qh_g + ((size_t)b * SS + m0) * DD;
    const bf16* qlp = ql_g + ((size_t)b * SS + m0) * DD;
    const bf16* khp = kh_g + ((size_t)b * SS + n0) * DD;
    const bf16* klp = kl_g + ((size_t)b * SS + n0) * DD;

    const int wm = (wid >> 2) * 64, wn = (wid & 3) * 64;
    float acc[4][8][4];
    #pragma unroll
    for (int i = 0; i < 4; i++)
        #pragma unroll
        for (int j = 0; j < 8; j++)
            #pragma unroll
            for (int e = 0; e < 4; e++) acc[i][j][e] = 0.f;

    auto load_half = [&](int h, uint32_t base) {
        load_tile64<128>(base,         qhp + h * 64, DD, tid);
        load_tile64<128>(base + 16384, qlp + h * 64, DD, tid);
        load_tile64<256>(base + 32768, khp + h * 64, DD, tid);
        load_tile64<256>(base + 65536, klp + h * 64, DD, tid);
        cp_commit();
    };
    auto compute = [&](uint32_t base) {
        const uint32_t Ah = base, Al = base + 16384, Bh = base + 32768, Bl = base + 65536;
        #pragma unroll
        for (int kt = 0; kt < 4; kt++) {
            uint32_t bh[8][2], bl[8][2], af[4][4];
            #pragma unroll
            for (int nt = 0; nt < 8; nt++) { ldsB(bh[nt], Bh, wn + nt*8, kt, lid); ldsB(bl[nt], Bl, wn + nt*8, kt, lid); }
            #pragma unroll
            for (int mt = 0; mt < 4; mt++) ldsA(af[mt], Ah, wm + mt*16, kt, lid);
            #pragma unroll
            for (int mt = 0; mt < 4; mt++)
                #pragma unroll
                for (int nt = 0; nt < 8; nt++) mma16816(acc[mt][nt], af[mt], bh[nt]);
            #pragma unroll
            for (int mt = 0; mt < 4; mt++)
                #pragma unroll
                for (int nt = 0; nt < 8; nt++) mma16816(acc[mt][nt], af[mt], bl[nt]);
            #pragma unroll
            for (int mt = 0; mt < 4; mt++) ldsA(af[mt], Al, wm + mt*16, kt, lid);
            #pragma unroll
            for (int mt = 0; mt < 4; mt++)
                #pragma unroll
                for (int nt = 0; nt < 8; nt++) mma16816(acc[mt][nt], af[mt], bh[nt]);
        }
    };

    load_half(0, sb);
    load_half(1, sb + SIM_STG);
    cp_wait<1>(); __syncthreads();
    compute(sb);
    cp_wait<0>(); __syncthreads();
    compute(sb + SIM_STG);

    const float invS = 1.0f / (float)SS;
    const int lr = lid >> 2, lc = (lid & 3) * 2;
    float* attb = att + (size_t)b * SS * SS;
    bf16* hib = atth + (size_t)b * SS * SS;
    #pragma unroll
    for (int mt = 0; mt < 4; mt++) {
        #pragma unroll
        for (int h2 = 0; h2 < 2; h2++) {
            int row = m0 + wm + mt * 16 + h2 * 8 + lr;
            size_t ro = (size_t)row * SS;
            #pragma unroll
            for (int nt = 0; nt < 8; nt++) {
                int col = n0 + wn + nt * 8 + lc;
                float s0 = fmaxf(acc[mt][nt][h2*2+0] * invS, 0.f);
                float s1 = fmaxf(acc[mt][nt][h2*2+1] * invS, 0.f);
                float a0 = s0 * s0, a1 = s1 * s1;
                *(float2*)(attb + ro + col) = make_float2(a0, a1);
                bf162 hp;
                hp.x = __float2bfloat16(a0); hp.y = __float2bfloat16(a1);
                *(bf162*)(hib + ro + col) = hp;
            }
        }
    }
}

// ================= big GEMM 2: av = atth @ (vh+vl), fused *gate -> hi/lo ====
#define AT_STG 81920    // A 16K | vh 32K | vl 32K
#define AT_SMEM (2*AT_STG)
#define AT_NS 64

__global__ __launch_bounds__(256) void attnv_mma(
    const bf16* __restrict__ atth,
    const bf16* __restrict__ vth, const bf16* __restrict__ vtl,
    const float* __restrict__ gate,
    bf16* __restrict__ avgh, bf16* __restrict__ avgl)
{
    extern __shared__ __align__(128) char smem[];
    const uint32_t sb = smem_u32(smem);
    const int tid = threadIdx.x, wid = tid >> 5, lid = tid & 31;
    const int b = blockIdx.y, m0 = blockIdx.x * 128;
    const bf16* ahp = atth + (size_t)b * SS * SS + (size_t)m0 * SS;
    const bf16* vhp = vth + (size_t)b * SS;
    const bf16* vlp = vtl + (size_t)b * SS;

    const int wm = (wid >> 2) * 64, wn = (wid & 3) * 64;
    float acc[4][8][4];
    #pragma unroll
    for (int i = 0; i < 4; i++)
        #pragma unroll
        for (int j = 0; j < 8; j++)
            #pragma unroll
            for (int e = 0; e < 4; e++) acc[i][j][e] = 0.f;

    auto load_slab = [&](int j, int s) {
        uint32_t base = sb + s * AT_STG;
        load_tile64<128>(base,         ahp + j * 64, SS, tid);
        load_tile64<256>(base + 16384, vhp + j * 64, ROWS, tid);
        load_tile64<256>(base + 49152, vlp + j * 64, ROWS, tid);
        cp_commit();
    };
    auto compute = [&](int s) {
        uint32_t base = sb + s * AT_STG;
        const uint32_t Aa = base, Bh = base + 16384, Bl = base + 49152;
        #pragma unroll
        for (int kt = 0; kt < 4; kt++) {
            uint32_t bhf[8][2], blf[8][2], af[4][4];
            #pragma unroll
            for (int nt = 0; nt < 8; nt++) { ldsB(bhf[nt], Bh, wn + nt*8, kt, lid); ldsB(blf[nt], Bl, wn + nt*8, kt, lid); }
            #pragma unroll
            for (int mt = 0; mt < 4; mt++) ldsA(af[mt], Aa, wm + mt*16, kt, lid);
            #pragma unroll
            for (int mt = 0; mt < 4; mt++)
                #pragma unroll
                for (int nt = 0; nt < 8; nt++) mma16816(acc[mt][nt], af[mt], bhf[nt]);
            #pragma unroll
            for (int mt = 0; mt < 4; mt++)
                #pragma unroll
                for (int nt = 0; nt < 8; nt++) mma16816(acc[mt][nt], af[mt], blf[nt]);
        }
    };

    load_slab(0, 0);
    load_slab(1, 1);
    for (int j = 0; j < AT_NS; j++) {
        if (j + 1 < AT_NS) cp_wait<1>(); else cp_wait<0>();
        __syncthreads();
        compute(j & 1);
        if (j + 2 < AT_NS) { __syncthreads(); load_slab(j + 2, j & 1); }
    }

    const int lr = lid >> 2, lc = (lid & 3) * 2;
    #pragma unroll
    for (int mt = 0; mt < 4; mt++) {
        #pragma unroll
        for (int h2 = 0; h2 < 2; h2++) {
            size_t grow = (size_t)b * SS + m0 + wm + mt * 16 + h2 * 8 + lr;
            const float* gp = gate + grow * HH;
            bf16* hp_ = avgh + grow * HH;
            bf16* lp_ = avgl + grow * HH;
            #pragma unroll
            for (int nt = 0; nt < 8; nt++) {
                int col = wn + nt * 8 + lc;
                float2 g2 = *(const float2*)(gp + col);
                float o0 = acc[mt][nt][h2*2+0] * g2.x;
                float o1 = acc[mt][nt][h2*2+1] * g2.y;
                bf162 hh, ll;
                split2(o0, hh.x, ll.x); split2(o1, hh.y, ll.y);
                *(bf162*)(hp_ + col) = hh;
                *(bf162*)(lp_ + col) = ll;
            }
        }
    }
}

// ================= launch =================
extern "C" void kernel_launch(void* const* d_in, const int* in_sizes, int n_in,
                              void* d_out, int out_size)
{
    const float* query  = (const float*)d_in[0];
    const float* value  = (const float*)d_in[2];
    const float* ln_g   = (const float*)d_in[3];
    const float* ln_b   = (const float*)d_in[4];
    const float* W_gate = (const float*)d_in[5];
    const float* b_gate = (const float*)d_in[6];
    const float* W_qk   = (const float*)d_in[7];
    const float* b_qk   = (const float*)d_in[8];
    const float* os_g   = (const float*)d_in[9];
    const float* os_b   = (const float*)d_in[10];
    const float* W_out  = (const float*)d_in[11];
    const float* b_out  = (const float*)d_in[12];

    float* out = (float*)d_out;
    float* att = out + (size_t)ROWS * DD;

    bf16 *p_nh, *p_nl, *p_vih, *p_vil, *p_wgh, *p_wgl, *p_wqh, *p_wql, *p_woh, *p_wol;
    bf16 *p_vrh, *p_vrl, *p_vTh, *p_vTl, *p_qh, *p_ql, *p_kh, *p_kl, *p_avgh, *p_avgl, *p_atth;
    float *p_gate;
    cudaGetSymbolAddress((void**)&p_nh, g_nh);
    cudaGetSymbolAddress((void**)&p_nl, g_nl);
    cudaGetSymbolAddress((void**)&p_vih, g_vih);
    cudaGetSymbolAddress((void**)&p_vil, g_vil);
    cudaGetSymbolAddress((void**)&p_wgh, g_wgh);
    cudaGetSymbolAddress((void**)&p_wgl, g_wgl);
    cudaGetSymbolAddress((void**)&p_wqh, g_wqh);
    cudaGetSymbolAddress((void**)&p_wql, g_wql);
    cudaGetSymbolAddress((void**)&p_woh, g_woh);
    cudaGetSymbolAddress((void**)&p_wol, g_wol);
    cudaGetSymbolAddress((void**)&p_gate, g_gate);
    cudaGetSymbolAddress((void**)&p_vrh, g_vrh);
    cudaGetSymbolAddress((void**)&p_vrl, g_vrl);
    cudaGetSymbolAddress((void**)&p_vTh, g_vTh);
    cudaGetSymbolAddress((void**)&p_vTl, g_vTl);
    cudaGetSymbolAddress((void**)&p_qh, g_qh);
    cudaGetSymbolAddress((void**)&p_ql, g_ql);
    cudaGetSymbolAddress((void**)&p_kh, g_kh);
    cudaGetSymbolAddress((void**)&p_kl, g_kl);
    cudaGetSymbolAddress((void**)&p_avgh, g_avgh);
    cudaGetSymbolAddress((void**)&p_avgl, g_avgl);
    cudaGetSymbolAddress((void**)&p_atth, g_atth);

    cudaFuncSetAttribute(sim_mma,  cudaFuncAttributeMaxDynamicSharedMemorySize, SIM_SMEM);
    cudaFuncSetAttribute(attnv_mma, cudaFuncAttributeMaxDynamicSharedMemorySize, AT_SMEM);
    cudaFuncSetAttribute((const void*)hmma_gemm<256,128,MODE_GATE>, cudaFuncAttributeMaxDynamicSharedMemorySize, 2*(32768+2*256*128));
    cudaFuncSetAttribute((const void*)hmma_gemm<256,128,MODE_V>,    cudaFuncAttributeMaxDynamicSharedMemorySize, 2*(32768+2*256*128));
    cudaFuncSetAttribute((const void*)hmma_gemm<128,128,MODE_QK>,   cudaFuncAttributeMaxDynamicSharedMemorySize, 2*(32768+2*128*128));
    cudaFuncSetAttribute((const void*)hmma_gemm<128,256,MODE_OUT>,  cudaFuncAttributeMaxDynamicSharedMemorySize, 2*(32768+2*128*128));

    // prep + splits
    prep_kernel<<<ROWS, 128>>>(query, ln_g, ln_b, p_nh, p_nl);
    split_kernel<<<(ROWS*DD + 255)/256, 256>>>(value, p_vih, p_vil, ROWS*DD);
    wsplit_all<<<320, 256>>>(W_gate, W_qk, W_out, p_wgh, p_wgl, p_wqh, p_wql, p_woh, p_wol);

    // projections (HMMA)
    hmma_gemm<256,128,MODE_GATE><<<128, 256, 2*(32768+2*256*128)>>>(
        p_nh, p_nl, p_wgh, p_wgl, b_gate, nullptr, nullptr,
        p_gate, nullptr, nullptr, nullptr, nullptr);
    hmma_gemm<256,128,MODE_V><<<128, 256, 2*(32768+2*256*128)>>>(
        p_vih, p_vil, p_wgh, p_wgl, b_gate, nullptr, nullptr,
        nullptr, p_vrh, p_vrl, nullptr, nullptr);
    hmma_gemm<128,128,MODE_QK><<<128, 256, 2*(32768+2*128*128)>>>(
        p_nh, p_nl, p_wqh, p_wql, b_qk, os_g, os_b,
        nullptr, p_qh, p_ql, p_kh, p_kl);
    transpose2<<<dim3(HH/32, ROWS/32, 2), dim3(32, 8)>>>(p_vrh, p_vrl, p_vTh, p_vTl);

    // attention
    sim_mma<<<dim3(SS/256, SS/128, BB), 256, SIM_SMEM>>>(p_qh, p_ql, p_kh, p_kl,
        att, p_atth);
    attnv_mma<<<dim3(SS/128, BB), 256, AT_SMEM>>>(p_atth, p_vTh, p_vTl, p_gate,
        p_avgh, p_avgl);

    // output projection
    hmma_gemm<128,256,MODE_OUT><<<128, 256, 2*(32768+2*128*128)>>>(
        p_avgh, p_avgl, p_woh, p_wol, b_out, nullptr, nullptr,
        out, nullptr, nullptr, nullptr, nullptr);
}